// round 2
// baseline (speedup 1.0000x reference)
#include <cuda_runtime.h>
#include <cuda_bf16.h>
#include <cstdint>

#define MAX_NODES 100000
#define MAX_EDGES 3200000
#define HID 64
#define IN_DIM 256

// Scratch (allocation-free rule: device globals)
__device__ float g_h[(size_t)MAX_NODES * HID];
__device__ float g_agg[(size_t)MAX_NODES * HID];
__device__ float g_dis[MAX_NODES];
__device__ int   g_deg[MAX_NODES];
__device__ int   g_row[MAX_NODES + 1];
__device__ int   g_cursor[MAX_NODES];
__device__ int   g_csr[MAX_EDGES];

// ---------------------------------------------------------------------------
// degree / normalization / CSR build
// ---------------------------------------------------------------------------
__global__ void k_zero_deg(int M) {
    int i = blockIdx.x * blockDim.x + threadIdx.x;
    if (i < M) g_deg[i] = 0;
}

__global__ void k_hist(const int* __restrict__ dst, int E) {
    int e = blockIdx.x * blockDim.x + threadIdx.x;
    if (e < E) atomicAdd(&g_deg[dst[e]], 1);
}

__global__ void k_dis(int M) {
    int i = blockIdx.x * blockDim.x + threadIdx.x;
    if (i < M) g_dis[i] = rsqrtf((float)g_deg[i] + 1.0f);  // +1 self loop
}

// single-block exclusive scan of g_deg -> g_row, g_cursor
__global__ void k_scan(int M, int E) {
    __shared__ int sums[1024];
    int t = threadIdx.x;
    int chunk = (M + 1023) >> 10;
    int lo = t * chunk;
    int hi = lo + chunk; if (hi > M) hi = M;
    int s = 0;
    for (int i = lo; i < hi; i++) s += g_deg[i];
    sums[t] = s;
    __syncthreads();
    // inclusive Hillis-Steele scan
    for (int off = 1; off < 1024; off <<= 1) {
        int v = (t >= off) ? sums[t - off] : 0;
        __syncthreads();
        sums[t] += v;
        __syncthreads();
    }
    int run = (t == 0) ? 0 : sums[t - 1];
    for (int i = lo; i < hi; i++) {
        g_row[i] = run;
        g_cursor[i] = run;
        run += g_deg[i];
    }
    if (t == 0) g_row[M] = E;
}

__global__ void k_fill(const int* __restrict__ src, const int* __restrict__ dst, int E) {
    int e = blockIdx.x * blockDim.x + threadIdx.x;
    if (e < E) {
        int d = dst[e];
        int pos = atomicAdd(&g_cursor[d], 1);
        g_csr[pos] = src[e];
    }
}

// ---------------------------------------------------------------------------
// GEMM: C[M x 64] = A[M x K] * B[K x 64]; BM=128 BN=64 BK=32, 128 thr, 8x8/thr
// ---------------------------------------------------------------------------
#define BM 128
#define BN 64
#define BK 32

__global__ __launch_bounds__(128) void k_gemm(
    const float* __restrict__ A, const float* __restrict__ B,
    float* __restrict__ C, int M, int K)
{
    __shared__ float As[BK][BM + 4];
    __shared__ float Bs[BK][BN];

    int tid = threadIdx.x;
    int ty = tid >> 3;         // 0..15
    int tx = tid & 7;          // 0..7
    int blockRow = blockIdx.x * BM;

    int la_r = tid >> 3;            // 0..15
    int la_c = (tid & 7) * 4;       // 0..28
    int lb_r = tid >> 4;            // 0..7
    int lb_c = (tid & 15) * 4;      // 0..60

    float acc[8][8];
    #pragma unroll
    for (int i = 0; i < 8; i++)
        #pragma unroll
        for (int j = 0; j < 8; j++) acc[i][j] = 0.f;

    for (int k0 = 0; k0 < K; k0 += BK) {
        #pragma unroll
        for (int p = 0; p < 8; p++) {
            int r = la_r + 16 * p;
            int gr = blockRow + r;
            float4 v = make_float4(0.f, 0.f, 0.f, 0.f);
            if (gr < M) v = *(const float4*)(A + (size_t)gr * K + k0 + la_c);
            As[la_c + 0][r] = v.x;
            As[la_c + 1][r] = v.y;
            As[la_c + 2][r] = v.z;
            As[la_c + 3][r] = v.w;
        }
        #pragma unroll
        for (int p = 0; p < 4; p++) {
            int r = lb_r + 8 * p;
            *(float4*)&Bs[r][lb_c] = *(const float4*)(B + (size_t)(k0 + r) * BN + lb_c);
        }
        __syncthreads();

        #pragma unroll
        for (int k = 0; k < BK; k++) {
            float a[8], b[8];
            float4 a0 = *(const float4*)&As[k][ty * 8];
            float4 a1 = *(const float4*)&As[k][ty * 8 + 4];
            a[0]=a0.x; a[1]=a0.y; a[2]=a0.z; a[3]=a0.w;
            a[4]=a1.x; a[5]=a1.y; a[6]=a1.z; a[7]=a1.w;
            float4 b0 = *(const float4*)&Bs[k][tx * 8];
            float4 b1 = *(const float4*)&Bs[k][tx * 8 + 4];
            b[0]=b0.x; b[1]=b0.y; b[2]=b0.z; b[3]=b0.w;
            b[4]=b1.x; b[5]=b1.y; b[6]=b1.z; b[7]=b1.w;
            #pragma unroll
            for (int i = 0; i < 8; i++)
                #pragma unroll
                for (int j = 0; j < 8; j++)
                    acc[i][j] += a[i] * b[j];
        }
        __syncthreads();
    }

    #pragma unroll
    for (int i = 0; i < 8; i++) {
        int gr = blockRow + ty * 8 + i;
        if (gr < M) {
            float4 v0 = make_float4(acc[i][0], acc[i][1], acc[i][2], acc[i][3]);
            float4 v1 = make_float4(acc[i][4], acc[i][5], acc[i][6], acc[i][7]);
            *(float4*)(C + (size_t)gr * HID + tx * 8)     = v0;
            *(float4*)(C + (size_t)gr * HID + tx * 8 + 4) = v1;
        }
    }
}

// ---------------------------------------------------------------------------
// CSR pull: out[i] = sum_{s in N(i)} dis[s]*dis[i]*h[s] + dis[i]^2*h[i] + bias
// one warp per node; half-warp per neighbor (16 lanes x float4 = 64 floats);
// 2 neighbors in flight per half-warp for MLP.
// ---------------------------------------------------------------------------
__global__ __launch_bounds__(256) void k_pull(
    const float* __restrict__ h, const float* __restrict__ bias,
    float* __restrict__ out, int M, int do_relu)
{
    int gw = (blockIdx.x * blockDim.x + threadIdx.x) >> 5;
    if (gw >= M) return;
    int lane = threadIdx.x & 31;
    int half = lane >> 4;
    int q = lane & 15;

    int start = g_row[gw];
    int end   = g_row[gw + 1];
    float dd = g_dis[gw];

    float4 acc0 = make_float4(0.f, 0.f, 0.f, 0.f);
    float4 acc1 = make_float4(0.f, 0.f, 0.f, 0.f);

    int j = start + half;
    for (; j + 2 < end; j += 4) {
        int s0 = __ldg(g_csr + j);
        int s1 = __ldg(g_csr + j + 2);
        float w0 = __ldg(g_dis + s0) * dd;
        float w1 = __ldg(g_dis + s1) * dd;
        float4 v0 = *(const float4*)(h + (size_t)s0 * HID + q * 4);
        float4 v1 = *(const float4*)(h + (size_t)s1 * HID + q * 4);
        acc0.x += w0 * v0.x; acc0.y += w0 * v0.y;
        acc0.z += w0 * v0.z; acc0.w += w0 * v0.w;
        acc1.x += w1 * v1.x; acc1.y += w1 * v1.y;
        acc1.z += w1 * v1.z; acc1.w += w1 * v1.w;
    }
    for (; j < end; j += 2) {
        int s = __ldg(g_csr + j);
        float w = __ldg(g_dis + s) * dd;
        float4 v = *(const float4*)(h + (size_t)s * HID + q * 4);
        acc0.x += w * v.x; acc0.y += w * v.y;
        acc0.z += w * v.z; acc0.w += w * v.w;
    }
    acc0.x += acc1.x; acc0.y += acc1.y; acc0.z += acc1.z; acc0.w += acc1.w;

    // combine the two half-warps
    acc0.x += __shfl_xor_sync(0xffffffffu, acc0.x, 16);
    acc0.y += __shfl_xor_sync(0xffffffffu, acc0.y, 16);
    acc0.z += __shfl_xor_sync(0xffffffffu, acc0.z, 16);
    acc0.w += __shfl_xor_sync(0xffffffffu, acc0.w, 16);

    if (half == 0) {
        float4 hv = *(const float4*)(h + (size_t)gw * HID + q * 4);
        float4 bq = *(const float4*)(bias + q * 4);
        float w = dd * dd;
        float4 r;
        r.x = acc0.x + w * hv.x + bq.x;
        r.y = acc0.y + w * hv.y + bq.y;
        r.z = acc0.z + w * hv.z + bq.z;
        r.w = acc0.w + w * hv.w + bq.w;
        if (do_relu) {
            r.x = fmaxf(r.x, 0.f); r.y = fmaxf(r.y, 0.f);
            r.z = fmaxf(r.z, 0.f); r.w = fmaxf(r.w, 0.f);
        }
        *(float4*)(out + (size_t)gw * HID + q * 4) = r;
    }
}

// ---------------------------------------------------------------------------
extern "C" void kernel_launch(void* const* d_in, const int* in_sizes, int n_in,
                              void* d_out, int out_size)
{
    const float* x  = (const float*)d_in[0];
    const int*   ei = (const int*)d_in[1];
    const float* W1 = (const float*)d_in[2];
    const float* b1 = (const float*)d_in[3];
    const float* W2 = (const float*)d_in[4];
    const float* b2 = (const float*)d_in[5];
    float* out = (float*)d_out;

    int M = in_sizes[0] / IN_DIM;
    int E = in_sizes[1] / 2;
    const int* src = ei;
    const int* dst = ei + E;

    float *ph, *pagg;
    cudaGetSymbolAddress((void**)&ph, g_h);
    cudaGetSymbolAddress((void**)&pagg, g_agg);

    int tb = 256;
    int gM = (M + tb - 1) / tb;
    int gE = (E + tb - 1) / tb;
    int gGemm = (M + BM - 1) / BM;
    long long pw = (long long)M * 32;
    int gPull = (int)((pw + tb - 1) / tb);

    // normalization + CSR build
    k_zero_deg<<<gM, tb>>>(M);
    k_hist<<<gE, tb>>>(dst, E);
    k_dis<<<gM, tb>>>(M);
    k_scan<<<1, 1024>>>(M, E);
    k_fill<<<gE, tb>>>(src, dst, E);

    // layer 1
    k_gemm<<<gGemm, 128>>>(x, W1, ph, M, IN_DIM);
    k_pull<<<gPull, tb>>>(ph, b1, pagg, M, 1);

    // layer 2
    k_gemm<<<gGemm, 128>>>(pagg, W2, ph, M, HID);
    k_pull<<<gPull, tb>>>(ph, b2, out, M, 0);
}

// round 5
// speedup vs baseline: 2.2712x; 2.2712x over previous
#include <cuda_runtime.h>
#include <cuda_fp16.h>
#include <cstdint>

#define MAX_NODES 100000
#define MAX_EDGES 3200000
#define HID 64
#define IN_DIM 256
#define SCAN_B 1024           // elements per scan block
#define MAX_PARTS 128         // ceil(MAX_NODES/SCAN_B) = 98 <= 128

// Scratch (allocation-free rule: device globals)
__device__ __half g_h[(size_t)MAX_NODES * HID];    // fp16 gemm outputs (gather buffer)
__device__ float  g_agg[(size_t)MAX_NODES * HID];  // fp32 pull output (gemm2 input)
__device__ float  g_dis[MAX_NODES];
__device__ int    g_deg[MAX_NODES];
__device__ int    g_row[MAX_NODES + 1];
__device__ int    g_cursor[MAX_NODES];
__device__ int    g_csr[MAX_EDGES];
__device__ int    g_part[MAX_PARTS];
__device__ int    g_partx[MAX_PARTS];

// ---------------------------------------------------------------------------
// degree / normalization
// ---------------------------------------------------------------------------
__global__ void k_zero_deg(int M) {
    int i = blockIdx.x * blockDim.x + threadIdx.x;
    if (i < M) g_deg[i] = 0;
}

__global__ void k_hist(const int* __restrict__ dst, int E) {
    int e = blockIdx.x * blockDim.x + threadIdx.x;
    if (e < E) atomicAdd(&g_deg[dst[e]], 1);
}

__global__ void k_dis(int M) {
    int i = blockIdx.x * blockDim.x + threadIdx.x;
    if (i < M) g_dis[i] = rsqrtf((float)g_deg[i] + 1.0f);  // +1 self loop
}

// ---------------------------------------------------------------------------
// hierarchical exclusive scan of g_deg -> g_row / g_cursor
// ---------------------------------------------------------------------------
__global__ __launch_bounds__(256) void k_scan1(int M) {
    __shared__ int wsum[8], wexcl[8];
    int b = blockIdx.x, t = threadIdx.x;
    int base = b * SCAN_B + t * 4;
    int v[4], s = 0;
    #pragma unroll
    for (int i = 0; i < 4; i++) {
        v[i] = (base + i < M) ? g_deg[base + i] : 0;
        s += v[i];
    }
    int lane = t & 31, wid = t >> 5;
    int x = s;
    #pragma unroll
    for (int off = 1; off < 32; off <<= 1) {
        int y = __shfl_up_sync(0xffffffffu, x, off);
        if (lane >= off) x += y;
    }
    if (lane == 31) wsum[wid] = x;
    __syncthreads();
    if (t == 0) {
        int r = 0;
        #pragma unroll
        for (int w = 0; w < 8; w++) { wexcl[w] = r; r += wsum[w]; }
        g_part[b] = r;
    }
    __syncthreads();
    int run = wexcl[wid] + (x - s);
    #pragma unroll
    for (int i = 0; i < 4; i++) {
        if (base + i < M) g_row[base + i] = run;
        run += v[i];
    }
}

__global__ void k_scan2(int nParts, int M, int E) {
    __shared__ int sh[MAX_PARTS];
    int t = threadIdx.x;
    sh[t] = (t < nParts) ? g_part[t] : 0;
    __syncthreads();
    for (int off = 1; off < MAX_PARTS; off <<= 1) {
        int y = (t >= off) ? sh[t - off] : 0;
        __syncthreads();
        sh[t] += y;
        __syncthreads();
    }
    if (t < nParts) g_partx[t] = (t == 0) ? 0 : sh[t - 1];
    if (t == 0) g_row[M] = E;
}

__global__ __launch_bounds__(256) void k_scan3(int M) {
    int b = blockIdx.x;
    int off = g_partx[b];
    int base = b * SCAN_B + threadIdx.x * 4;
    #pragma unroll
    for (int i = 0; i < 4; i++) {
        int idx = base + i;
        if (idx < M) {
            int r = g_row[idx] + off;
            g_row[idx] = r;
            g_cursor[idx] = r;
        }
    }
}

__global__ void k_fill(const int* __restrict__ src, const int* __restrict__ dst, int E) {
    int e = blockIdx.x * blockDim.x + threadIdx.x;
    if (e < E) {
        int d = dst[e];
        int pos = atomicAdd(&g_cursor[d], 1);
        g_csr[pos] = src[e];
    }
}

// ---------------------------------------------------------------------------
// GEMM: C[M x 64](fp16) = A[M x K](fp32) * B[K x 64](fp32)
// BM=128 BN=64 BK=32, 128 thr, 8x8 per thread
// ---------------------------------------------------------------------------
#define BM 128
#define BN 64
#define BK 32

__global__ __launch_bounds__(128) void k_gemm(
    const float* __restrict__ A, const float* __restrict__ B,
    __half* __restrict__ C, int M, int K)
{
    __shared__ float As[BK][BM + 4];
    __shared__ float Bs[BK][BN];

    int tid = threadIdx.x;
    int ty = tid >> 3;         // 0..15
    int tx = tid & 7;          // 0..7
    int blockRow = blockIdx.x * BM;

    int la_r = tid >> 3;            // 0..15
    int la_c = (tid & 7) * 4;       // 0..28
    int lb_r = tid >> 4;            // 0..7
    int lb_c = (tid & 15) * 4;      // 0..60

    float acc[8][8];
    #pragma unroll
    for (int i = 0; i < 8; i++)
        #pragma unroll
        for (int j = 0; j < 8; j++) acc[i][j] = 0.f;

    for (int k0 = 0; k0 < K; k0 += BK) {
        #pragma unroll
        for (int p = 0; p < 8; p++) {
            int r = la_r + 16 * p;
            int gr = blockRow + r;
            float4 v = make_float4(0.f, 0.f, 0.f, 0.f);
            if (gr < M) v = *(const float4*)(A + (size_t)gr * K + k0 + la_c);
            As[la_c + 0][r] = v.x;
            As[la_c + 1][r] = v.y;
            As[la_c + 2][r] = v.z;
            As[la_c + 3][r] = v.w;
        }
        #pragma unroll
        for (int p = 0; p < 4; p++) {
            int r = lb_r + 8 * p;
            *(float4*)&Bs[r][lb_c] = *(const float4*)(B + (size_t)(k0 + r) * BN + lb_c);
        }
        __syncthreads();

        #pragma unroll
        for (int k = 0; k < BK; k++) {
            float a[8], b[8];
            float4 a0 = *(const float4*)&As[k][ty * 8];
            float4 a1 = *(const float4*)&As[k][ty * 8 + 4];
            a[0]=a0.x; a[1]=a0.y; a[2]=a0.z; a[3]=a0.w;
            a[4]=a1.x; a[5]=a1.y; a[6]=a1.z; a[7]=a1.w;
            float4 b0 = *(const float4*)&Bs[k][tx * 8];
            float4 b1 = *(const float4*)&Bs[k][tx * 8 + 4];
            b[0]=b0.x; b[1]=b0.y; b[2]=b0.z; b[3]=b0.w;
            b[4]=b1.x; b[5]=b1.y; b[6]=b1.z; b[7]=b1.w;
            #pragma unroll
            for (int i = 0; i < 8; i++)
                #pragma unroll
                for (int j = 0; j < 8; j++)
                    acc[i][j] += a[i] * b[j];
        }
        __syncthreads();
    }

    #pragma unroll
    for (int i = 0; i < 8; i++) {
        int gr = blockRow + ty * 8 + i;
        if (gr < M) {
            __half2 hb[4];
            #pragma unroll
            for (int j = 0; j < 4; j++)
                hb[j] = __floats2half2_rn(acc[i][2 * j], acc[i][2 * j + 1]);
            // 8 halfs = 16 bytes -> uint4 store (uint2 here was the R2/R3 bug)
            *(uint4*)(C + (size_t)gr * HID + tx * 8) = *(uint4*)hb;
        }
    }
}

// ---------------------------------------------------------------------------
// CSR pull (fp16 gather): out[i] = sum_s w*h[s] + dis[i]^2*h[i] + bias
// one warp per node; half-warp per neighbor (16 lanes x 4 halfs = 64);
// 2 neighbors in flight per half-warp.
// ---------------------------------------------------------------------------
__global__ __launch_bounds__(256) void k_pull(
    const __half* __restrict__ h, const float* __restrict__ bias,
    float* __restrict__ out, int M, int do_relu)
{
    int gw = (blockIdx.x * blockDim.x + threadIdx.x) >> 5;
    if (gw >= M) return;
    int lane = threadIdx.x & 31;
    int half_id = lane >> 4;
    int q = lane & 15;

    int start = g_row[gw];
    int end   = g_row[gw + 1];
    float dd = g_dis[gw];

    float4 acc0 = make_float4(0.f, 0.f, 0.f, 0.f);
    float4 acc1 = make_float4(0.f, 0.f, 0.f, 0.f);

    int j = start + half_id;
    for (; j + 2 < end; j += 4) {
        int s0 = __ldg(g_csr + j);
        int s1 = __ldg(g_csr + j + 2);
        float w0 = __ldg(g_dis + s0) * dd;
        float w1 = __ldg(g_dis + s1) * dd;
        uint2 r0 = *(const uint2*)(h + (size_t)s0 * HID + q * 4);
        uint2 r1 = *(const uint2*)(h + (size_t)s1 * HID + q * 4);
        float2 a = __half22float2(*(__half2*)&r0.x);
        float2 b = __half22float2(*(__half2*)&r0.y);
        float2 c = __half22float2(*(__half2*)&r1.x);
        float2 d = __half22float2(*(__half2*)&r1.y);
        acc0.x += w0 * a.x; acc0.y += w0 * a.y;
        acc0.z += w0 * b.x; acc0.w += w0 * b.y;
        acc1.x += w1 * c.x; acc1.y += w1 * c.y;
        acc1.z += w1 * d.x; acc1.w += w1 * d.y;
    }
    for (; j < end; j += 2) {
        int s = __ldg(g_csr + j);
        float w = __ldg(g_dis + s) * dd;
        uint2 r0 = *(const uint2*)(h + (size_t)s * HID + q * 4);
        float2 a = __half22float2(*(__half2*)&r0.x);
        float2 b = __half22float2(*(__half2*)&r0.y);
        acc0.x += w * a.x; acc0.y += w * a.y;
        acc0.z += w * b.x; acc0.w += w * b.y;
    }
    acc0.x += acc1.x; acc0.y += acc1.y; acc0.z += acc1.z; acc0.w += acc1.w;

    acc0.x += __shfl_xor_sync(0xffffffffu, acc0.x, 16);
    acc0.y += __shfl_xor_sync(0xffffffffu, acc0.y, 16);
    acc0.z += __shfl_xor_sync(0xffffffffu, acc0.z, 16);
    acc0.w += __shfl_xor_sync(0xffffffffu, acc0.w, 16);

    if (half_id == 0) {
        uint2 rs = *(const uint2*)(h + (size_t)gw * HID + q * 4);
        float2 a = __half22float2(*(__half2*)&rs.x);
        float2 b = __half22float2(*(__half2*)&rs.y);
        float4 bq = *(const float4*)(bias + q * 4);
        float w = dd * dd;
        float4 r;
        r.x = acc0.x + w * a.x + bq.x;
        r.y = acc0.y + w * a.y + bq.y;
        r.z = acc0.z + w * b.x + bq.z;
        r.w = acc0.w + w * b.y + bq.w;
        if (do_relu) {
            r.x = fmaxf(r.x, 0.f); r.y = fmaxf(r.y, 0.f);
            r.z = fmaxf(r.z, 0.f); r.w = fmaxf(r.w, 0.f);
        }
        *(float4*)(out + (size_t)gw * HID + q * 4) = r;
    }
}

// ---------------------------------------------------------------------------
extern "C" void kernel_launch(void* const* d_in, const int* in_sizes, int n_in,
                              void* d_out, int out_size)
{
    const float* x  = (const float*)d_in[0];
    const int*   ei = (const int*)d_in[1];
    const float* W1 = (const float*)d_in[2];
    const float* b1 = (const float*)d_in[3];
    const float* W2 = (const float*)d_in[4];
    const float* b2 = (const float*)d_in[5];
    float* out = (float*)d_out;

    int M = in_sizes[0] / IN_DIM;
    int E = in_sizes[1] / 2;
    const int* src = ei;
    const int* dst = ei + E;

    __half* ph;
    float* pagg;
    cudaGetSymbolAddress((void**)&ph, g_h);
    cudaGetSymbolAddress((void**)&pagg, g_agg);

    int tb = 256;
    int gM = (M + tb - 1) / tb;
    int gE = (E + tb - 1) / tb;
    int gGemm = (M + BM - 1) / BM;
    int nParts = (M + SCAN_B - 1) / SCAN_B;
    long long pw = (long long)M * 32;
    int gPull = (int)((pw + tb - 1) / tb);

    // normalization + CSR build
    k_zero_deg<<<gM, tb>>>(M);
    k_hist<<<gE, tb>>>(dst, E);
    k_dis<<<gM, tb>>>(M);
    k_scan1<<<nParts, 256>>>(M);
    k_scan2<<<1, MAX_PARTS>>>(nParts, M, E);
    k_scan3<<<nParts, 256>>>(M);
    k_fill<<<gE, tb>>>(src, dst, E);

    // layer 1
    k_gemm<<<gGemm, 128>>>(x, W1, ph, M, IN_DIM);
    k_pull<<<gPull, tb>>>(ph, b1, pagg, M, 1);

    // layer 2
    k_gemm<<<gGemm, 128>>>(pagg, W2, ph, M, HID);
    k_pull<<<gPull, tb>>>(ph, b2, out, M, 0);
}

// round 6
// speedup vs baseline: 2.6937x; 1.1860x over previous
#include <cuda_runtime.h>
#include <cuda_fp16.h>
#include <cstdint>

#define MAX_NODES 100000
#define MAX_EDGES 3200000
#define HID 64
#define IN_DIM 256
#define SCAN_B 1024
#define MAX_PARTS 128

// Scratch (allocation-free rule: device globals)
__device__ __half g_h[(size_t)MAX_NODES * HID];    // fp16 gemm outputs (gather buffer)
__device__ float  g_agg[(size_t)MAX_NODES * HID];  // fp32 pull output (gemm2 input)
__device__ float  g_dis[MAX_NODES];
__device__ int    g_deg[MAX_NODES];
__device__ int    g_row[MAX_NODES + 1];
__device__ int    g_cursor[MAX_NODES];
__device__ int    g_csr[MAX_EDGES];
__device__ int    g_part[MAX_PARTS];
__device__ int    g_partx[MAX_PARTS];

// ---------------------------------------------------------------------------
// degree / normalization
// ---------------------------------------------------------------------------
__global__ void k_zero_deg(int M) {
    int i = blockIdx.x * blockDim.x + threadIdx.x;
    if (i < M) g_deg[i] = 0;
}

__global__ void k_hist(const int* __restrict__ dst, int E) {
    int e = blockIdx.x * blockDim.x + threadIdx.x;
    if (e < E) atomicAdd(&g_deg[dst[e]], 1);
}

__global__ void k_dis(int M) {
    int i = blockIdx.x * blockDim.x + threadIdx.x;
    if (i < M) g_dis[i] = rsqrtf((float)g_deg[i] + 1.0f);  // +1 self loop
}

// ---------------------------------------------------------------------------
// hierarchical exclusive scan of g_deg -> g_row / g_cursor
// ---------------------------------------------------------------------------
__global__ __launch_bounds__(256) void k_scan1(int M) {
    __shared__ int wsum[8], wexcl[8];
    int b = blockIdx.x, t = threadIdx.x;
    int base = b * SCAN_B + t * 4;
    int v[4], s = 0;
    #pragma unroll
    for (int i = 0; i < 4; i++) {
        v[i] = (base + i < M) ? g_deg[base + i] : 0;
        s += v[i];
    }
    int lane = t & 31, wid = t >> 5;
    int x = s;
    #pragma unroll
    for (int off = 1; off < 32; off <<= 1) {
        int y = __shfl_up_sync(0xffffffffu, x, off);
        if (lane >= off) x += y;
    }
    if (lane == 31) wsum[wid] = x;
    __syncthreads();
    if (t == 0) {
        int r = 0;
        #pragma unroll
        for (int w = 0; w < 8; w++) { wexcl[w] = r; r += wsum[w]; }
        g_part[b] = r;
    }
    __syncthreads();
    int run = wexcl[wid] + (x - s);
    #pragma unroll
    for (int i = 0; i < 4; i++) {
        if (base + i < M) g_row[base + i] = run;
        run += v[i];
    }
}

__global__ void k_scan2(int nParts, int M, int E) {
    __shared__ int sh[MAX_PARTS];
    int t = threadIdx.x;
    sh[t] = (t < nParts) ? g_part[t] : 0;
    __syncthreads();
    for (int off = 1; off < MAX_PARTS; off <<= 1) {
        int y = (t >= off) ? sh[t - off] : 0;
        __syncthreads();
        sh[t] += y;
        __syncthreads();
    }
    if (t < nParts) g_partx[t] = (t == 0) ? 0 : sh[t - 1];
    if (t == 0) g_row[M] = E;
}

__global__ __launch_bounds__(256) void k_scan3(int M) {
    int b = blockIdx.x;
    int off = g_partx[b];
    int base = b * SCAN_B + threadIdx.x * 4;
    #pragma unroll
    for (int i = 0; i < 4; i++) {
        int idx = base + i;
        if (idx < M) {
            int r = g_row[idx] + off;
            g_row[idx] = r;
            g_cursor[idx] = r;
        }
    }
}

__global__ void k_fill(const int* __restrict__ src, const int* __restrict__ dst, int E) {
    int e = blockIdx.x * blockDim.x + threadIdx.x;
    if (e < E) {
        int d = dst[e];
        int pos = atomicAdd(&g_cursor[d], 1);
        g_csr[pos] = src[e];
    }
}

// ---------------------------------------------------------------------------
// Tensor-core GEMM (tf32): C[M x 64](fp16) = A[M x K](fp32) * B[K x 64](fp32)
// BM=128 BN=64 BK=16; 8 warps; warp tile 64x16 via mma.m16n8k8.tf32
// ---------------------------------------------------------------------------
#define GBM 128
#define GBN 64
#define GBK 16

__device__ __forceinline__ uint32_t f2tf32(float f) {
    uint32_t r;
    asm("cvt.rna.tf32.f32 %0, %1;" : "=r"(r) : "f"(f));
    return r;
}

__device__ __forceinline__ void mma_tf32(float4& c,
    uint32_t a0, uint32_t a1, uint32_t a2, uint32_t a3,
    uint32_t b0, uint32_t b1)
{
    asm volatile(
        "mma.sync.aligned.m16n8k8.row.col.f32.tf32.tf32.f32 "
        "{%0,%1,%2,%3}, {%4,%5,%6,%7}, {%8,%9}, {%0,%1,%2,%3};"
        : "+f"(c.x), "+f"(c.y), "+f"(c.z), "+f"(c.w)
        : "r"(a0), "r"(a1), "r"(a2), "r"(a3), "r"(b0), "r"(b1));
}

__global__ __launch_bounds__(256) void k_gemm_tc(
    const float* __restrict__ A, const float* __restrict__ B,
    __half* __restrict__ C, int M, int K)
{
    __shared__ float As[GBM][GBK + 4];   // stride 20: conflict-free frag loads
    __shared__ float Bs[GBK][GBN];

    int tid = threadIdx.x;
    int warp = tid >> 5, lane = tid & 31;
    int wm = warp & 1;    // 2 warp rows x 64
    int wn = warp >> 1;   // 4 warp cols x 16
    int blockRow = blockIdx.x * GBM;

    int qr = lane >> 2;   // 0..7
    int qk = lane & 3;    // 0..3

    float4 c[4][2];
    #pragma unroll
    for (int i = 0; i < 4; i++)
        #pragma unroll
        for (int j = 0; j < 2; j++) c[i][j] = make_float4(0.f, 0.f, 0.f, 0.f);

    // global->smem maps
    int ar = tid >> 2;            // 0..63 (two rows: ar, ar+64)
    int ac = (tid & 3) * 4;       // 0,4,8,12
    int br = tid >> 4;            // 0..15
    int bc = (tid & 15) * 4;      // 0..60

    for (int k0 = 0; k0 < K; k0 += GBK) {
        #pragma unroll
        for (int p = 0; p < 2; p++) {
            int r = ar + p * 64;
            int gr = blockRow + r;
            float4 v = make_float4(0.f, 0.f, 0.f, 0.f);
            if (gr < M) v = *(const float4*)(A + (size_t)gr * K + k0 + ac);
            *(float4*)&As[r][ac] = v;
        }
        *(float4*)&Bs[br][bc] = *(const float4*)(B + (size_t)(k0 + br) * GBN + bc);
        __syncthreads();

        #pragma unroll
        for (int kk = 0; kk < 2; kk++) {
            int kb = kk * 8;
            uint32_t bf[2][2];
            #pragma unroll
            for (int ni = 0; ni < 2; ni++) {
                int n = wn * 16 + ni * 8 + qr;
                bf[ni][0] = f2tf32(Bs[kb + qk][n]);
                bf[ni][1] = f2tf32(Bs[kb + qk + 4][n]);
            }
            #pragma unroll
            for (int mi = 0; mi < 4; mi++) {
                int r0 = wm * 64 + mi * 16 + qr;
                uint32_t a0 = f2tf32(As[r0][kb + qk]);
                uint32_t a1 = f2tf32(As[r0 + 8][kb + qk]);
                uint32_t a2 = f2tf32(As[r0][kb + qk + 4]);
                uint32_t a3 = f2tf32(As[r0 + 8][kb + qk + 4]);
                mma_tf32(c[mi][0], a0, a1, a2, a3, bf[0][0], bf[0][1]);
                mma_tf32(c[mi][1], a0, a1, a2, a3, bf[1][0], bf[1][1]);
            }
        }
        __syncthreads();
    }

    // epilogue: fp16 store
    #pragma unroll
    for (int mi = 0; mi < 4; mi++) {
        int r0 = blockRow + wm * 64 + mi * 16 + qr;
        int ncol = wn * 16 + 2 * qk;
        #pragma unroll
        for (int ni = 0; ni < 2; ni++) {
            int n = ncol + ni * 8;
            if (r0 < M)
                *(__half2*)(C + (size_t)r0 * HID + n) = __floats2half2_rn(c[mi][ni].x, c[mi][ni].y);
            if (r0 + 8 < M)
                *(__half2*)(C + (size_t)(r0 + 8) * HID + n) = __floats2half2_rn(c[mi][ni].z, c[mi][ni].w);
        }
    }
}

// ---------------------------------------------------------------------------
// CSR pull (fp16 gather): out[i] = sum_s w*h[s] + dis[i]^2*h[i] + bias
// ---------------------------------------------------------------------------
__global__ __launch_bounds__(256) void k_pull(
    const __half* __restrict__ h, const float* __restrict__ bias,
    float* __restrict__ out, int M, int do_relu)
{
    int gw = (blockIdx.x * blockDim.x + threadIdx.x) >> 5;
    if (gw >= M) return;
    int lane = threadIdx.x & 31;
    int half_id = lane >> 4;
    int q = lane & 15;

    int start = g_row[gw];
    int end   = g_row[gw + 1];
    float dd = g_dis[gw];

    float4 acc0 = make_float4(0.f, 0.f, 0.f, 0.f);
    float4 acc1 = make_float4(0.f, 0.f, 0.f, 0.f);

    int j = start + half_id;
    for (; j + 2 < end; j += 4) {
        int s0 = __ldg(g_csr + j);
        int s1 = __ldg(g_csr + j + 2);
        float w0 = __ldg(g_dis + s0) * dd;
        float w1 = __ldg(g_dis + s1) * dd;
        uint2 r0 = *(const uint2*)(h + (size_t)s0 * HID + q * 4);
        uint2 r1 = *(const uint2*)(h + (size_t)s1 * HID + q * 4);
        float2 a = __half22float2(*(__half2*)&r0.x);
        float2 b = __half22float2(*(__half2*)&r0.y);
        float2 cc = __half22float2(*(__half2*)&r1.x);
        float2 d = __half22float2(*(__half2*)&r1.y);
        acc0.x += w0 * a.x; acc0.y += w0 * a.y;
        acc0.z += w0 * b.x; acc0.w += w0 * b.y;
        acc1.x += w1 * cc.x; acc1.y += w1 * cc.y;
        acc1.z += w1 * d.x; acc1.w += w1 * d.y;
    }
    for (; j < end; j += 2) {
        int s = __ldg(g_csr + j);
        float w = __ldg(g_dis + s) * dd;
        uint2 r0 = *(const uint2*)(h + (size_t)s * HID + q * 4);
        float2 a = __half22float2(*(__half2*)&r0.x);
        float2 b = __half22float2(*(__half2*)&r0.y);
        acc0.x += w * a.x; acc0.y += w * a.y;
        acc0.z += w * b.x; acc0.w += w * b.y;
    }
    acc0.x += acc1.x; acc0.y += acc1.y; acc0.z += acc1.z; acc0.w += acc1.w;

    acc0.x += __shfl_xor_sync(0xffffffffu, acc0.x, 16);
    acc0.y += __shfl_xor_sync(0xffffffffu, acc0.y, 16);
    acc0.z += __shfl_xor_sync(0xffffffffu, acc0.z, 16);
    acc0.w += __shfl_xor_sync(0xffffffffu, acc0.w, 16);

    if (half_id == 0) {
        uint2 rs = *(const uint2*)(h + (size_t)gw * HID + q * 4);
        float2 a = __half22float2(*(__half2*)&rs.x);
        float2 b = __half22float2(*(__half2*)&rs.y);
        float4 bq = *(const float4*)(bias + q * 4);
        float w = dd * dd;
        float4 r;
        r.x = acc0.x + w * a.x + bq.x;
        r.y = acc0.y + w * a.y + bq.y;
        r.z = acc0.z + w * b.x + bq.z;
        r.w = acc0.w + w * b.y + bq.w;
        if (do_relu) {
            r.x = fmaxf(r.x, 0.f); r.y = fmaxf(r.y, 0.f);
            r.z = fmaxf(r.z, 0.f); r.w = fmaxf(r.w, 0.f);
        }
        *(float4*)(out + (size_t)gw * HID + q * 4) = r;
    }
}

// ---------------------------------------------------------------------------
extern "C" void kernel_launch(void* const* d_in, const int* in_sizes, int n_in,
                              void* d_out, int out_size)
{
    const float* x  = (const float*)d_in[0];
    const int*   ei = (const int*)d_in[1];
    const float* W1 = (const float*)d_in[2];
    const float* b1 = (const float*)d_in[3];
    const float* W2 = (const float*)d_in[4];
    const float* b2 = (const float*)d_in[5];
    float* out = (float*)d_out;

    int M = in_sizes[0] / IN_DIM;
    int E = in_sizes[1] / 2;
    const int* src = ei;
    const int* dst = ei + E;

    __half* ph;
    float* pagg;
    cudaGetSymbolAddress((void**)&ph, g_h);
    cudaGetSymbolAddress((void**)&pagg, g_agg);

    int tb = 256;
    int gM = (M + tb - 1) / tb;
    int gE = (E + tb - 1) / tb;
    int gGemm = (M + GBM - 1) / GBM;
    int nParts = (M + SCAN_B - 1) / SCAN_B;
    long long pw = (long long)M * 32;
    int gPull = (int)((pw + tb - 1) / tb);

    // normalization + CSR build
    k_zero_deg<<<gM, tb>>>(M);
    k_hist<<<gE, tb>>>(dst, E);
    k_dis<<<gM, tb>>>(M);
    k_scan1<<<nParts, 256>>>(M);
    k_scan2<<<1, MAX_PARTS>>>(nParts, M, E);
    k_scan3<<<nParts, 256>>>(M);
    k_fill<<<gE, tb>>>(src, dst, E);

    // layer 1
    k_gemm_tc<<<gGemm, 256>>>(x, W1, ph, M, IN_DIM);
    k_pull<<<gPull, tb>>>(ph, b1, pagg, M, 1);

    // layer 2
    k_gemm_tc<<<gGemm, 256>>>(pagg, W2, ph, M, HID);
    k_pull<<<gPull, tb>>>(ph, b2, out, M, 0);
}

// round 7
// speedup vs baseline: 2.9819x; 1.1070x over previous
#include <cuda_runtime.h>
#include <cuda_fp16.h>
#include <cstdint>

#define MAX_NODES 100000
#define MAX_EDGES 3200000
#define HID 64
#define IN_DIM 256
#define SCAN_B 1024
#define MAX_PARTS 128

// Scratch (allocation-free rule: device globals)
__device__ __half g_h[(size_t)MAX_NODES * HID];    // dis-scaled gemm outputs (gather buffer)
__device__ __half g_agg[(size_t)MAX_NODES * HID];  // fp16 pull1 output (gemm2 input)
__device__ float  g_dis[MAX_NODES];
__device__ int    g_deg[MAX_NODES];
__device__ int    g_row[MAX_NODES + 1];
__device__ int    g_cursor[MAX_NODES];
__device__ int    g_csr[MAX_EDGES];
__device__ int    g_part[MAX_PARTS];
__device__ int    g_partx[MAX_PARTS];

// ---------------------------------------------------------------------------
// degree / normalization
// ---------------------------------------------------------------------------
__global__ void k_zero_deg(int M) {
    int i = blockIdx.x * blockDim.x + threadIdx.x;
    if (i < M) g_deg[i] = 0;
}

__global__ void k_hist(const int* __restrict__ dst, int E) {
    int e = blockIdx.x * blockDim.x + threadIdx.x;
    if (e < E) atomicAdd(&g_deg[dst[e]], 1);
}

__global__ void k_dis(int M) {
    int i = blockIdx.x * blockDim.x + threadIdx.x;
    if (i < M) g_dis[i] = rsqrtf((float)g_deg[i] + 1.0f);  // +1 self loop
}

// ---------------------------------------------------------------------------
// hierarchical exclusive scan of g_deg -> g_row / g_cursor
// ---------------------------------------------------------------------------
__global__ __launch_bounds__(256) void k_scan1(int M) {
    __shared__ int wsum[8], wexcl[8];
    int b = blockIdx.x, t = threadIdx.x;
    int base = b * SCAN_B + t * 4;
    int v[4], s = 0;
    #pragma unroll
    for (int i = 0; i < 4; i++) {
        v[i] = (base + i < M) ? g_deg[base + i] : 0;
        s += v[i];
    }
    int lane = t & 31, wid = t >> 5;
    int x = s;
    #pragma unroll
    for (int off = 1; off < 32; off <<= 1) {
        int y = __shfl_up_sync(0xffffffffu, x, off);
        if (lane >= off) x += y;
    }
    if (lane == 31) wsum[wid] = x;
    __syncthreads();
    if (t == 0) {
        int r = 0;
        #pragma unroll
        for (int w = 0; w < 8; w++) { wexcl[w] = r; r += wsum[w]; }
        g_part[b] = r;
    }
    __syncthreads();
    int run = wexcl[wid] + (x - s);
    #pragma unroll
    for (int i = 0; i < 4; i++) {
        if (base + i < M) g_row[base + i] = run;
        run += v[i];
    }
}

__global__ void k_scan2(int nParts, int M, int E) {
    __shared__ int sh[MAX_PARTS];
    int t = threadIdx.x;
    sh[t] = (t < nParts) ? g_part[t] : 0;
    __syncthreads();
    for (int off = 1; off < MAX_PARTS; off <<= 1) {
        int y = (t >= off) ? sh[t - off] : 0;
        __syncthreads();
        sh[t] += y;
        __syncthreads();
    }
    if (t < nParts) g_partx[t] = (t == 0) ? 0 : sh[t - 1];
    if (t == 0) g_row[M] = E;
}

__global__ __launch_bounds__(256) void k_scan3(int M) {
    int b = blockIdx.x;
    int off = g_partx[b];
    int base = b * SCAN_B + threadIdx.x * 4;
    #pragma unroll
    for (int i = 0; i < 4; i++) {
        int idx = base + i;
        if (idx < M) {
            int r = g_row[idx] + off;
            g_row[idx] = r;
            g_cursor[idx] = r;
        }
    }
}

__global__ void k_fill(const int* __restrict__ src, const int* __restrict__ dst, int E) {
    int e = blockIdx.x * blockDim.x + threadIdx.x;
    if (e < E) {
        int d = dst[e];
        int pos = atomicAdd(&g_cursor[d], 1);
        g_csr[pos] = src[e];
    }
}

// ---------------------------------------------------------------------------
// Tensor-core GEMM (tf32): C[M x 64](fp16, row-scaled by dis) = A[M x K] * B[K x 64]
// BM=128 BN=64 BK=16; 8 warps; warp tile 64x16 via mma.m16n8k8.tf32
// ---------------------------------------------------------------------------
#define GBM 128
#define GBN 64
#define GBK 16

__device__ __forceinline__ uint32_t f2tf32(float f) {
    uint32_t r;
    asm("cvt.rna.tf32.f32 %0, %1;" : "=r"(r) : "f"(f));
    return r;
}

__device__ __forceinline__ void mma_tf32(float4& c,
    uint32_t a0, uint32_t a1, uint32_t a2, uint32_t a3,
    uint32_t b0, uint32_t b1)
{
    asm volatile(
        "mma.sync.aligned.m16n8k8.row.col.f32.tf32.tf32.f32 "
        "{%0,%1,%2,%3}, {%4,%5,%6,%7}, {%8,%9}, {%0,%1,%2,%3};"
        : "+f"(c.x), "+f"(c.y), "+f"(c.z), "+f"(c.w)
        : "r"(a0), "r"(a1), "r"(a2), "r"(a3), "r"(b0), "r"(b1));
}

__device__ __forceinline__ float4 ld4(const float* p) { return *(const float4*)p; }
__device__ __forceinline__ float4 ld4(const __half* p) {
    uint2 r = *(const uint2*)p;
    float2 a = __half22float2(*(__half2*)&r.x);
    float2 b = __half22float2(*(__half2*)&r.y);
    return make_float4(a.x, a.y, b.x, b.y);
}

template <typename T>
__global__ __launch_bounds__(256) void k_gemm_tc(
    const T* __restrict__ A, const float* __restrict__ B,
    __half* __restrict__ C, int M, int K)
{
    __shared__ float As[GBM][GBK + 4];   // stride 20: conflict-free frag loads
    __shared__ float Bs[GBK][GBN];

    int tid = threadIdx.x;
    int warp = tid >> 5, lane = tid & 31;
    int wm = warp & 1;    // 2 warp rows x 64
    int wn = warp >> 1;   // 4 warp cols x 16
    int blockRow = blockIdx.x * GBM;

    int qr = lane >> 2;   // 0..7
    int qk = lane & 3;    // 0..3

    float4 c[4][2];
    #pragma unroll
    for (int i = 0; i < 4; i++)
        #pragma unroll
        for (int j = 0; j < 2; j++) c[i][j] = make_float4(0.f, 0.f, 0.f, 0.f);

    int ar = tid >> 2;            // 0..63 (two rows: ar, ar+64)
    int ac = (tid & 3) * 4;       // 0,4,8,12
    int br = tid >> 4;            // 0..15
    int bc = (tid & 15) * 4;      // 0..60

    for (int k0 = 0; k0 < K; k0 += GBK) {
        #pragma unroll
        for (int p = 0; p < 2; p++) {
            int r = ar + p * 64;
            int gr = blockRow + r;
            float4 v = make_float4(0.f, 0.f, 0.f, 0.f);
            if (gr < M) v = ld4(A + (size_t)gr * K + k0 + ac);
            *(float4*)&As[r][ac] = v;
        }
        *(float4*)&Bs[br][bc] = *(const float4*)(B + (size_t)(k0 + br) * GBN + bc);
        __syncthreads();

        #pragma unroll
        for (int kk = 0; kk < 2; kk++) {
            int kb = kk * 8;
            uint32_t bf[2][2];
            #pragma unroll
            for (int ni = 0; ni < 2; ni++) {
                int n = wn * 16 + ni * 8 + qr;
                bf[ni][0] = f2tf32(Bs[kb + qk][n]);
                bf[ni][1] = f2tf32(Bs[kb + qk + 4][n]);
            }
            #pragma unroll
            for (int mi = 0; mi < 4; mi++) {
                int r0 = wm * 64 + mi * 16 + qr;
                uint32_t a0 = f2tf32(As[r0][kb + qk]);
                uint32_t a1 = f2tf32(As[r0 + 8][kb + qk]);
                uint32_t a2 = f2tf32(As[r0][kb + qk + 4]);
                uint32_t a3 = f2tf32(As[r0 + 8][kb + qk + 4]);
                mma_tf32(c[mi][0], a0, a1, a2, a3, bf[0][0], bf[0][1]);
                mma_tf32(c[mi][1], a0, a1, a2, a3, bf[1][0], bf[1][1]);
            }
        }
        __syncthreads();
    }

    // epilogue: scale rows by dis[r], store fp16
    #pragma unroll
    for (int mi = 0; mi < 4; mi++) {
        int r0 = blockRow + wm * 64 + mi * 16 + qr;
        int r1 = r0 + 8;
        float d0 = (r0 < M) ? g_dis[r0] : 0.f;
        float d1 = (r1 < M) ? g_dis[r1] : 0.f;
        int ncol = wn * 16 + 2 * qk;
        #pragma unroll
        for (int ni = 0; ni < 2; ni++) {
            int n = ncol + ni * 8;
            if (r0 < M)
                *(__half2*)(C + (size_t)r0 * HID + n) = __floats2half2_rn(d0 * c[mi][ni].x, d0 * c[mi][ni].y);
            if (r1 < M)
                *(__half2*)(C + (size_t)r1 * HID + n) = __floats2half2_rn(d1 * c[mi][ni].z, d1 * c[mi][ni].w);
        }
    }
}

// ---------------------------------------------------------------------------
// CSR pull over pre-scaled rows: out[i] = dis_i*(sum_s sh[s] + sh[i]) + bias
// one warp per node; half-warp per neighbor; 4 rows in flight per half-warp.
// ---------------------------------------------------------------------------
__device__ __forceinline__ void acc_add(float4& a, uint2 r) {
    float2 lo = __half22float2(*(__half2*)&r.x);
    float2 hi = __half22float2(*(__half2*)&r.y);
    a.x += lo.x; a.y += lo.y; a.z += hi.x; a.w += hi.y;
}

__device__ __forceinline__ void store_out(float* out, size_t off, float4 v) {
    *(float4*)(out + off) = v;
}
__device__ __forceinline__ void store_out(__half* out, size_t off, float4 v) {
    __half2 h2[2];
    h2[0] = __floats2half2_rn(v.x, v.y);
    h2[1] = __floats2half2_rn(v.z, v.w);
    *(uint2*)(out + off) = *(uint2*)h2;
}

template <typename TO>
__global__ __launch_bounds__(256) void k_pull(
    const __half* __restrict__ h, const float* __restrict__ bias,
    TO* __restrict__ out, int M, int do_relu)
{
    int gw = (blockIdx.x * blockDim.x + threadIdx.x) >> 5;
    if (gw >= M) return;
    int lane = threadIdx.x & 31;
    int half_id = lane >> 4;
    int q = lane & 15;

    int start = g_row[gw];
    int end   = g_row[gw + 1];
    float dd = g_dis[gw];

    float4 acc0 = make_float4(0.f, 0.f, 0.f, 0.f);
    float4 acc1 = make_float4(0.f, 0.f, 0.f, 0.f);

    int j = start + half_id;
    for (; j + 6 < end; j += 8) {
        int s0 = __ldg(g_csr + j);
        int s1 = __ldg(g_csr + j + 2);
        int s2 = __ldg(g_csr + j + 4);
        int s3 = __ldg(g_csr + j + 6);
        uint2 r0 = *(const uint2*)(h + (size_t)s0 * HID + q * 4);
        uint2 r1 = *(const uint2*)(h + (size_t)s1 * HID + q * 4);
        uint2 r2 = *(const uint2*)(h + (size_t)s2 * HID + q * 4);
        uint2 r3 = *(const uint2*)(h + (size_t)s3 * HID + q * 4);
        acc_add(acc0, r0);
        acc_add(acc1, r1);
        acc_add(acc0, r2);
        acc_add(acc1, r3);
    }
    for (; j < end; j += 2) {
        int s = __ldg(g_csr + j);
        uint2 r = *(const uint2*)(h + (size_t)s * HID + q * 4);
        acc_add(acc0, r);
    }
    acc0.x += acc1.x; acc0.y += acc1.y; acc0.z += acc1.z; acc0.w += acc1.w;

    acc0.x += __shfl_xor_sync(0xffffffffu, acc0.x, 16);
    acc0.y += __shfl_xor_sync(0xffffffffu, acc0.y, 16);
    acc0.z += __shfl_xor_sync(0xffffffffu, acc0.z, 16);
    acc0.w += __shfl_xor_sync(0xffffffffu, acc0.w, 16);

    if (half_id == 0) {
        uint2 rs = *(const uint2*)(h + (size_t)gw * HID + q * 4);
        acc_add(acc0, rs);   // self loop (already dis_i-scaled)
        float4 bq = *(const float4*)(bias + q * 4);
        float4 r;
        r.x = dd * acc0.x + bq.x;
        r.y = dd * acc0.y + bq.y;
        r.z = dd * acc0.z + bq.z;
        r.w = dd * acc0.w + bq.w;
        if (do_relu) {
            r.x = fmaxf(r.x, 0.f); r.y = fmaxf(r.y, 0.f);
            r.z = fmaxf(r.z, 0.f); r.w = fmaxf(r.w, 0.f);
        }
        store_out(out, (size_t)gw * HID + q * 4, r);
    }
}

// ---------------------------------------------------------------------------
extern "C" void kernel_launch(void* const* d_in, const int* in_sizes, int n_in,
                              void* d_out, int out_size)
{
    const float* x  = (const float*)d_in[0];
    const int*   ei = (const int*)d_in[1];
    const float* W1 = (const float*)d_in[2];
    const float* b1 = (const float*)d_in[3];
    const float* W2 = (const float*)d_in[4];
    const float* b2 = (const float*)d_in[5];
    float* out = (float*)d_out;

    int M = in_sizes[0] / IN_DIM;
    int E = in_sizes[1] / 2;
    const int* src = ei;
    const int* dst = ei + E;

    __half *ph, *pagg;
    cudaGetSymbolAddress((void**)&ph, g_h);
    cudaGetSymbolAddress((void**)&pagg, g_agg);

    int tb = 256;
    int gM = (M + tb - 1) / tb;
    int gE = (E + tb - 1) / tb;
    int gGemm = (M + GBM - 1) / GBM;
    int nParts = (M + SCAN_B - 1) / SCAN_B;
    long long pw = (long long)M * 32;
    int gPull = (int)((pw + tb - 1) / tb);

    // normalization + CSR build
    k_zero_deg<<<gM, tb>>>(M);
    k_hist<<<gE, tb>>>(dst, E);
    k_dis<<<gM, tb>>>(M);
    k_scan1<<<nParts, 256>>>(M);
    k_scan2<<<1, MAX_PARTS>>>(nParts, M, E);
    k_scan3<<<nParts, 256>>>(M);
    k_fill<<<gE, tb>>>(src, dst, E);

    // layer 1
    k_gemm_tc<float><<<gGemm, 256>>>(x, W1, ph, M, IN_DIM);
    k_pull<__half><<<gPull, tb>>>(ph, b1, pagg, M, 1);

    // layer 2
    k_gemm_tc<__half><<<gGemm, 256>>>(pagg, W2, ph, M, HID);
    k_pull<float><<<gPull, tb>>>(ph, b2, out, M, 0);
}

// round 8
// speedup vs baseline: 3.1415x; 1.0535x over previous
#include <cuda_runtime.h>
#include <cuda_fp16.h>
#include <cstdint>

#define MAX_NODES 100000
#define MAX_EDGES 3200000
#define HID 64
#define IN_DIM 256
#define SCAN_B 1024
#define MAX_PARTS 128

// Scratch (allocation-free rule: device globals)
__device__ __half g_h[(size_t)MAX_NODES * HID];    // dis-scaled gemm outputs (gather buffer)
__device__ __half g_agg[(size_t)MAX_NODES * HID];  // fp16 pull1 output (gemm2 input)
__device__ float  g_dis[MAX_NODES];
__device__ int    g_deg[MAX_NODES];
__device__ int    g_row[MAX_NODES + 1];
__device__ int    g_cursor[MAX_NODES];
__device__ int    g_csr[MAX_EDGES];
__device__ int    g_part[MAX_PARTS];
__device__ int    g_partx[MAX_PARTS];

// ---------------------------------------------------------------------------
// degree histogram (4 edges/thread, int4)
// ---------------------------------------------------------------------------
__global__ void k_zero_deg(int M) {
    int i = blockIdx.x * blockDim.x + threadIdx.x;
    if (i < M) g_deg[i] = 0;
}

__global__ void k_hist(const int* __restrict__ dst, int E) {
    int i = blockIdx.x * blockDim.x + threadIdx.x;
    int e = i * 4;
    if (e + 3 < E && (((uintptr_t)dst & 15) == 0)) {
        int4 d = *(const int4*)(dst + e);
        atomicAdd(&g_deg[d.x], 1);
        atomicAdd(&g_deg[d.y], 1);
        atomicAdd(&g_deg[d.z], 1);
        atomicAdd(&g_deg[d.w], 1);
    } else {
        for (int k = e; k < E && k < e + 4; k++)
            atomicAdd(&g_deg[dst[k]], 1);
    }
}

// ---------------------------------------------------------------------------
// scan1 also writes g_dis (fused k_dis)
// ---------------------------------------------------------------------------
__global__ __launch_bounds__(256) void k_scan1(int M) {
    __shared__ int wsum[8], wexcl[8];
    int b = blockIdx.x, t = threadIdx.x;
    int base = b * SCAN_B + t * 4;
    int v[4], s = 0;
    #pragma unroll
    for (int i = 0; i < 4; i++) {
        v[i] = (base + i < M) ? g_deg[base + i] : 0;
        s += v[i];
    }
    #pragma unroll
    for (int i = 0; i < 4; i++)
        if (base + i < M) g_dis[base + i] = rsqrtf((float)v[i] + 1.0f);
    int lane = t & 31, wid = t >> 5;
    int x = s;
    #pragma unroll
    for (int off = 1; off < 32; off <<= 1) {
        int y = __shfl_up_sync(0xffffffffu, x, off);
        if (lane >= off) x += y;
    }
    if (lane == 31) wsum[wid] = x;
    __syncthreads();
    if (t == 0) {
        int r = 0;
        #pragma unroll
        for (int w = 0; w < 8; w++) { wexcl[w] = r; r += wsum[w]; }
        g_part[b] = r;
    }
    __syncthreads();
    int run = wexcl[wid] + (x - s);
    #pragma unroll
    for (int i = 0; i < 4; i++) {
        if (base + i < M) g_row[base + i] = run;
        run += v[i];
    }
}

__global__ void k_scan2(int nParts, int M, int E) {
    __shared__ int sh[MAX_PARTS];
    int t = threadIdx.x;
    sh[t] = (t < nParts) ? g_part[t] : 0;
    __syncthreads();
    for (int off = 1; off < MAX_PARTS; off <<= 1) {
        int y = (t >= off) ? sh[t - off] : 0;
        __syncthreads();
        sh[t] += y;
        __syncthreads();
    }
    if (t < nParts) g_partx[t] = (t == 0) ? 0 : sh[t - 1];
    if (t == 0) g_row[M] = E;
}

__global__ __launch_bounds__(256) void k_scan3(int M) {
    int b = blockIdx.x;
    int off = g_partx[b];
    int base = b * SCAN_B + threadIdx.x * 4;
    #pragma unroll
    for (int i = 0; i < 4; i++) {
        int idx = base + i;
        if (idx < M) {
            int r = g_row[idx] + off;
            g_row[idx] = r;
            g_cursor[idx] = r;
        }
    }
}

__global__ void k_fill(const int* __restrict__ src, const int* __restrict__ dst, int E) {
    int i = blockIdx.x * blockDim.x + threadIdx.x;
    int e = i * 4;
    if (e + 3 < E && (((uintptr_t)src & 15) == 0) && (((uintptr_t)dst & 15) == 0)) {
        int4 s = *(const int4*)(src + e);
        int4 d = *(const int4*)(dst + e);
        g_csr[atomicAdd(&g_cursor[d.x], 1)] = s.x;
        g_csr[atomicAdd(&g_cursor[d.y], 1)] = s.y;
        g_csr[atomicAdd(&g_cursor[d.z], 1)] = s.z;
        g_csr[atomicAdd(&g_cursor[d.w], 1)] = s.w;
    } else {
        for (int k = e; k < E && k < e + 4; k++)
            g_csr[atomicAdd(&g_cursor[dst[k]], 1)] = src[k];
    }
}

// ---------------------------------------------------------------------------
// Tensor-core GEMM (tf32): C[M x 64](fp16, row-scaled by dis) = A[M x K] * B[K x 64]
// BM=128 BN=64 BK=16; 8 warps; warp tile 64x16 via mma.m16n8k8.tf32
// Epilogue staged through smem for coalesced uint4 stores.
// ---------------------------------------------------------------------------
#define GBM 128
#define GBN 64
#define GBK 16
#define CS_STRIDE (HID + 8)

__device__ __forceinline__ uint32_t f2tf32(float f) {
    uint32_t r;
    asm("cvt.rna.tf32.f32 %0, %1;" : "=r"(r) : "f"(f));
    return r;
}

__device__ __forceinline__ void mma_tf32(float4& c,
    uint32_t a0, uint32_t a1, uint32_t a2, uint32_t a3,
    uint32_t b0, uint32_t b1)
{
    asm volatile(
        "mma.sync.aligned.m16n8k8.row.col.f32.tf32.tf32.f32 "
        "{%0,%1,%2,%3}, {%4,%5,%6,%7}, {%8,%9}, {%0,%1,%2,%3};"
        : "+f"(c.x), "+f"(c.y), "+f"(c.z), "+f"(c.w)
        : "r"(a0), "r"(a1), "r"(a2), "r"(a3), "r"(b0), "r"(b1));
}

__device__ __forceinline__ float4 ld4(const float* p) { return *(const float4*)p; }
__device__ __forceinline__ float4 ld4(const __half* p) {
    uint2 r = *(const uint2*)p;
    float2 a = __half22float2(*(__half2*)&r.x);
    float2 b = __half22float2(*(__half2*)&r.y);
    return make_float4(a.x, a.y, b.x, b.y);
}

template <typename T>
__global__ __launch_bounds__(256) void k_gemm_tc(
    const T* __restrict__ A, const float* __restrict__ B,
    __half* __restrict__ C, int M, int K)
{
    __shared__ float As[GBM][GBK + 4];   // stride 20: conflict-free frag loads
    __shared__ float Bs[GBK][GBN];
    __shared__ __half Cs[GBM][CS_STRIDE];

    int tid = threadIdx.x;
    int warp = tid >> 5, lane = tid & 31;
    int wm = warp & 1;    // 2 warp rows x 64
    int wn = warp >> 1;   // 4 warp cols x 16
    int blockRow = blockIdx.x * GBM;

    int qr = lane >> 2;   // 0..7
    int qk = lane & 3;    // 0..3

    float4 c[4][2];
    #pragma unroll
    for (int i = 0; i < 4; i++)
        #pragma unroll
        for (int j = 0; j < 2; j++) c[i][j] = make_float4(0.f, 0.f, 0.f, 0.f);

    int ar = tid >> 2;            // 0..63 (two rows: ar, ar+64)
    int ac = (tid & 3) * 4;       // 0,4,8,12
    int br = tid >> 4;            // 0..15
    int bc = (tid & 15) * 4;      // 0..60

    for (int k0 = 0; k0 < K; k0 += GBK) {
        #pragma unroll
        for (int p = 0; p < 2; p++) {
            int r = ar + p * 64;
            int gr = blockRow + r;
            float4 v = make_float4(0.f, 0.f, 0.f, 0.f);
            if (gr < M) v = ld4(A + (size_t)gr * K + k0 + ac);
            *(float4*)&As[r][ac] = v;
        }
        *(float4*)&Bs[br][bc] = *(const float4*)(B + (size_t)(k0 + br) * GBN + bc);
        __syncthreads();

        #pragma unroll
        for (int kk = 0; kk < 2; kk++) {
            int kb = kk * 8;
            uint32_t bf[2][2];
            #pragma unroll
            for (int ni = 0; ni < 2; ni++) {
                int n = wn * 16 + ni * 8 + qr;
                bf[ni][0] = f2tf32(Bs[kb + qk][n]);
                bf[ni][1] = f2tf32(Bs[kb + qk + 4][n]);
            }
            #pragma unroll
            for (int mi = 0; mi < 4; mi++) {
                int r0 = wm * 64 + mi * 16 + qr;
                uint32_t a0 = f2tf32(As[r0][kb + qk]);
                uint32_t a1 = f2tf32(As[r0 + 8][kb + qk]);
                uint32_t a2 = f2tf32(As[r0][kb + qk + 4]);
                uint32_t a3 = f2tf32(As[r0 + 8][kb + qk + 4]);
                mma_tf32(c[mi][0], a0, a1, a2, a3, bf[0][0], bf[0][1]);
                mma_tf32(c[mi][1], a0, a1, a2, a3, bf[1][0], bf[1][1]);
            }
        }
        __syncthreads();
    }

    // epilogue: scale rows by dis[r], stage to smem, coalesced store
    #pragma unroll
    for (int mi = 0; mi < 4; mi++) {
        int rr0 = wm * 64 + mi * 16 + qr;
        int rr1 = rr0 + 8;
        int gr0 = blockRow + rr0, gr1 = blockRow + rr1;
        float d0 = (gr0 < M) ? g_dis[gr0] : 0.f;
        float d1 = (gr1 < M) ? g_dis[gr1] : 0.f;
        int ncol = wn * 16 + 2 * qk;
        #pragma unroll
        for (int ni = 0; ni < 2; ni++) {
            int n = ncol + ni * 8;
            *(__half2*)&Cs[rr0][n] = __floats2half2_rn(d0 * c[mi][ni].x, d0 * c[mi][ni].y);
            *(__half2*)&Cs[rr1][n] = __floats2half2_rn(d1 * c[mi][ni].z, d1 * c[mi][ni].w);
        }
    }
    __syncthreads();
    int cr = tid >> 3;            // 0..31
    int ccol = (tid & 7) * 8;     // 0..56 (halfs)
    #pragma unroll
    for (int p = 0; p < 4; p++) {
        int r = p * 32 + cr;
        int gr = blockRow + r;
        if (gr < M)
            *(uint4*)(C + (size_t)gr * HID + ccol) = *(uint4*)&Cs[r][ccol];
    }
}

// ---------------------------------------------------------------------------
// CSR pull over pre-scaled rows: out[i] = dis_i*(sum_s sh[s] + sh[i]) + bias
// one warp per node; half-warp per neighbor; 8 rows in flight per half-warp.
// ---------------------------------------------------------------------------
__device__ __forceinline__ void acc_add(float4& a, uint2 r) {
    float2 lo = __half22float2(*(__half2*)&r.x);
    float2 hi = __half22float2(*(__half2*)&r.y);
    a.x += lo.x; a.y += lo.y; a.z += hi.x; a.w += hi.y;
}

__device__ __forceinline__ void store_out(float* out, size_t off, float4 v) {
    *(float4*)(out + off) = v;
}
__device__ __forceinline__ void store_out(__half* out, size_t off, float4 v) {
    __half2 h2[2];
    h2[0] = __floats2half2_rn(v.x, v.y);
    h2[1] = __floats2half2_rn(v.z, v.w);
    *(uint2*)(out + off) = *(uint2*)h2;
}

template <typename TO>
__global__ __launch_bounds__(256) void k_pull(
    const __half* __restrict__ h, const float* __restrict__ bias,
    TO* __restrict__ out, int M, int do_relu)
{
    int gw = (blockIdx.x * blockDim.x + threadIdx.x) >> 5;
    if (gw >= M) return;
    int lane = threadIdx.x & 31;
    int half_id = lane >> 4;
    int q = lane & 15;

    int start = g_row[gw];
    int end   = g_row[gw + 1];
    float dd = g_dis[gw];

    float4 acc0 = make_float4(0.f, 0.f, 0.f, 0.f);
    float4 acc1 = make_float4(0.f, 0.f, 0.f, 0.f);

    int j = start + half_id;
    // 8 rows in flight per half-warp
    for (; j + 14 < end; j += 16) {
        int s0 = __ldg(g_csr + j);
        int s1 = __ldg(g_csr + j + 2);
        int s2 = __ldg(g_csr + j + 4);
        int s3 = __ldg(g_csr + j + 6);
        int s4 = __ldg(g_csr + j + 8);
        int s5 = __ldg(g_csr + j + 10);
        int s6 = __ldg(g_csr + j + 12);
        int s7 = __ldg(g_csr + j + 14);
        uint2 r0 = *(const uint2*)(h + (size_t)s0 * HID + q * 4);
        uint2 r1 = *(const uint2*)(h + (size_t)s1 * HID + q * 4);
        uint2 r2 = *(const uint2*)(h + (size_t)s2 * HID + q * 4);
        uint2 r3 = *(const uint2*)(h + (size_t)s3 * HID + q * 4);
        uint2 r4 = *(const uint2*)(h + (size_t)s4 * HID + q * 4);
        uint2 r5 = *(const uint2*)(h + (size_t)s5 * HID + q * 4);
        uint2 r6 = *(const uint2*)(h + (size_t)s6 * HID + q * 4);
        uint2 r7 = *(const uint2*)(h + (size_t)s7 * HID + q * 4);
        acc_add(acc0, r0); acc_add(acc1, r1);
        acc_add(acc0, r2); acc_add(acc1, r3);
        acc_add(acc0, r4); acc_add(acc1, r5);
        acc_add(acc0, r6); acc_add(acc1, r7);
    }
    for (; j + 6 < end; j += 8) {
        int s0 = __ldg(g_csr + j);
        int s1 = __ldg(g_csr + j + 2);
        int s2 = __ldg(g_csr + j + 4);
        int s3 = __ldg(g_csr + j + 6);
        uint2 r0 = *(const uint2*)(h + (size_t)s0 * HID + q * 4);
        uint2 r1 = *(const uint2*)(h + (size_t)s1 * HID + q * 4);
        uint2 r2 = *(const uint2*)(h + (size_t)s2 * HID + q * 4);
        uint2 r3 = *(const uint2*)(h + (size_t)s3 * HID + q * 4);
        acc_add(acc0, r0); acc_add(acc1, r1);
        acc_add(acc0, r2); acc_add(acc1, r3);
    }
    for (; j < end; j += 2) {
        int s = __ldg(g_csr + j);
        uint2 r = *(const uint2*)(h + (size_t)s * HID + q * 4);
        acc_add(acc0, r);
    }
    acc0.x += acc1.x; acc0.y += acc1.y; acc0.z += acc1.z; acc0.w += acc1.w;

    acc0.x += __shfl_xor_sync(0xffffffffu, acc0.x, 16);
    acc0.y += __shfl_xor_sync(0xffffffffu, acc0.y, 16);
    acc0.z += __shfl_xor_sync(0xffffffffu, acc0.z, 16);
    acc0.w += __shfl_xor_sync(0xffffffffu, acc0.w, 16);

    if (half_id == 0) {
        uint2 rs = *(const uint2*)(h + (size_t)gw * HID + q * 4);
        acc_add(acc0, rs);   // self loop (already dis_i-scaled)
        float4 bq = *(const float4*)(bias + q * 4);
        float4 r;
        r.x = dd * acc0.x + bq.x;
        r.y = dd * acc0.y + bq.y;
        r.z = dd * acc0.z + bq.z;
        r.w = dd * acc0.w + bq.w;
        if (do_relu) {
            r.x = fmaxf(r.x, 0.f); r.y = fmaxf(r.y, 0.f);
            r.z = fmaxf(r.z, 0.f); r.w = fmaxf(r.w, 0.f);
        }
        store_out(out, (size_t)gw * HID + q * 4, r);
    }
}

// ---------------------------------------------------------------------------
extern "C" void kernel_launch(void* const* d_in, const int* in_sizes, int n_in,
                              void* d_out, int out_size)
{
    const float* x  = (const float*)d_in[0];
    const int*   ei = (const int*)d_in[1];
    const float* W1 = (const float*)d_in[2];
    const float* b1 = (const float*)d_in[3];
    const float* W2 = (const float*)d_in[4];
    const float* b2 = (const float*)d_in[5];
    float* out = (float*)d_out;

    int M = in_sizes[0] / IN_DIM;
    int E = in_sizes[1] / 2;
    const int* src = ei;
    const int* dst = ei + E;

    __half *ph, *pagg;
    cudaGetSymbolAddress((void**)&ph, g_h);
    cudaGetSymbolAddress((void**)&pagg, g_agg);

    int tb = 256;
    int gM = (M + tb - 1) / tb;
    int gE4 = ((E + 3) / 4 + tb - 1) / tb;
    int gGemm = (M + GBM - 1) / GBM;
    int nParts = (M + SCAN_B - 1) / SCAN_B;
    long long pw = (long long)M * 32;
    int gPull = (int)((pw + tb - 1) / tb);

    // normalization + CSR build
    k_zero_deg<<<gM, tb>>>(M);
    k_hist<<<gE4, tb>>>(dst, E);
    k_scan1<<<nParts, 256>>>(M);
    k_scan2<<<1, MAX_PARTS>>>(nParts, M, E);
    k_scan3<<<nParts, 256>>>(M);
    k_fill<<<gE4, tb>>>(src, dst, E);

    // layer 1
    k_gemm_tc<float><<<gGemm, 256>>>(x, W1, ph, M, IN_DIM);
    k_pull<__half><<<gPull, tb>>>(ph, b1, pagg, M, 1);

    // layer 2
    k_gemm_tc<__half><<<gGemm, 256>>>(pagg, W2, ph, M, HID);
    k_pull<float><<<gPull, tb>>>(ph, b2, out, M, 0);
}

// round 9
// speedup vs baseline: 3.1628x; 1.0068x over previous
#include <cuda_runtime.h>
#include <cuda_fp16.h>
#include <cstdint>

#define MAX_NODES 100000
#define MAX_EDGES 3200000
#define HID 64
#define IN_DIM 256
#define SCAN_B 1024
#define MAX_PARTS 128

// Scratch (allocation-free rule: device globals)
__device__ __half g_h[(size_t)MAX_NODES * HID];    // dis-scaled gemm outputs (gather buffer)
__device__ __half g_agg[(size_t)MAX_NODES * HID];  // fp16 pull1 output (gemm2 input)
__device__ float  g_dis[MAX_NODES];
__device__ int    g_deg[MAX_NODES];
__device__ int    g_row[MAX_NODES + 1];
__device__ int    g_cursor[MAX_NODES];
__device__ int    g_csr[MAX_EDGES];
__device__ int    g_part[MAX_PARTS];

// ---------------------------------------------------------------------------
// degree histogram (4 edges/thread, int4)
// ---------------------------------------------------------------------------
__global__ void k_zero_deg(int M) {
    int i = blockIdx.x * blockDim.x + threadIdx.x;
    if (i < M) g_deg[i] = 0;
}

__global__ void k_hist(const int* __restrict__ dst, int E) {
    int i = blockIdx.x * blockDim.x + threadIdx.x;
    int e = i * 4;
    if (e + 3 < E && (((uintptr_t)dst & 15) == 0)) {
        int4 d = *(const int4*)(dst + e);
        atomicAdd(&g_deg[d.x], 1);
        atomicAdd(&g_deg[d.y], 1);
        atomicAdd(&g_deg[d.z], 1);
        atomicAdd(&g_deg[d.w], 1);
    } else {
        for (int k = e; k < E && k < e + 4; k++)
            atomicAdd(&g_deg[dst[k]], 1);
    }
}

// ---------------------------------------------------------------------------
// scan1: block-local exclusive scan + dis
// ---------------------------------------------------------------------------
__global__ __launch_bounds__(256) void k_scan1(int M) {
    __shared__ int wsum[8], wexcl[8];
    int b = blockIdx.x, t = threadIdx.x;
    int base = b * SCAN_B + t * 4;
    int v[4], s = 0;
    #pragma unroll
    for (int i = 0; i < 4; i++) {
        v[i] = (base + i < M) ? g_deg[base + i] : 0;
        s += v[i];
    }
    #pragma unroll
    for (int i = 0; i < 4; i++)
        if (base + i < M) g_dis[base + i] = rsqrtf((float)v[i] + 1.0f);
    int lane = t & 31, wid = t >> 5;
    int x = s;
    #pragma unroll
    for (int off = 1; off < 32; off <<= 1) {
        int y = __shfl_up_sync(0xffffffffu, x, off);
        if (lane >= off) x += y;
    }
    if (lane == 31) wsum[wid] = x;
    __syncthreads();
    if (t == 0) {
        int r = 0;
        #pragma unroll
        for (int w = 0; w < 8; w++) { wexcl[w] = r; r += wsum[w]; }
        g_part[b] = r;
    }
    __syncthreads();
    int run = wexcl[wid] + (x - s);
    #pragma unroll
    for (int i = 0; i < 4; i++) {
        if (base + i < M) g_row[base + i] = run;
        run += v[i];
    }
}

// scan3: each block computes its own partial prefix (<=98 ints) and applies it
__global__ __launch_bounds__(256) void k_scan3(int M, int E) {
    __shared__ int s_off;
    int b = blockIdx.x, t = threadIdx.x;
    if (t < 32) {
        int s = 0;
        for (int i = t; i < b; i += 32) s += g_part[i];
        #pragma unroll
        for (int o = 16; o; o >>= 1) s += __shfl_xor_sync(0xffffffffu, s, o);
        if (t == 0) s_off = s;
    }
    __syncthreads();
    int off = s_off;
    int base = b * SCAN_B + t * 4;
    #pragma unroll
    for (int i = 0; i < 4; i++) {
        int idx = base + i;
        if (idx < M) {
            int r = g_row[idx] + off;
            g_row[idx] = r;
            g_cursor[idx] = r;
        }
    }
    if (b == 0 && t == 0) g_row[M] = E;
}

__global__ void k_fill(const int* __restrict__ src, const int* __restrict__ dst, int E) {
    int i = blockIdx.x * blockDim.x + threadIdx.x;
    int e = i * 4;
    if (e + 3 < E && (((uintptr_t)src & 15) == 0) && (((uintptr_t)dst & 15) == 0)) {
        int4 s = *(const int4*)(src + e);
        int4 d = *(const int4*)(dst + e);
        g_csr[atomicAdd(&g_cursor[d.x], 1)] = s.x;
        g_csr[atomicAdd(&g_cursor[d.y], 1)] = s.y;
        g_csr[atomicAdd(&g_cursor[d.z], 1)] = s.z;
        g_csr[atomicAdd(&g_cursor[d.w], 1)] = s.w;
    } else {
        for (int k = e; k < E && k < e + 4; k++)
            g_csr[atomicAdd(&g_cursor[dst[k]], 1)] = src[k];
    }
}

// ---------------------------------------------------------------------------
// Tensor-core GEMM (tf32): C[M x 64](fp16, row-scaled by dis) = A[M x K] * B[K x 64]
// fp32 input path: 2-stage cp.async pipeline. fp16 path: simple sync loads.
// ---------------------------------------------------------------------------
#define GBM 128
#define GBN 64
#define GBK 16
#define CS_STRIDE (HID + 8)

__device__ __forceinline__ uint32_t f2tf32(float f) {
    uint32_t r;
    asm("cvt.rna.tf32.f32 %0, %1;" : "=r"(r) : "f"(f));
    return r;
}

__device__ __forceinline__ void mma_tf32(float4& c,
    uint32_t a0, uint32_t a1, uint32_t a2, uint32_t a3,
    uint32_t b0, uint32_t b1)
{
    asm volatile(
        "mma.sync.aligned.m16n8k8.row.col.f32.tf32.tf32.f32 "
        "{%0,%1,%2,%3}, {%4,%5,%6,%7}, {%8,%9}, {%0,%1,%2,%3};"
        : "+f"(c.x), "+f"(c.y), "+f"(c.z), "+f"(c.w)
        : "r"(a0), "r"(a1), "r"(a2), "r"(a3), "r"(b0), "r"(b1));
}

__device__ __forceinline__ void cp_async16(void* smem, const void* gmem, int src_bytes) {
    uint32_t s = (uint32_t)__cvta_generic_to_shared(smem);
    asm volatile("cp.async.ca.shared.global [%0], [%1], 16, %2;"
                 :: "r"(s), "l"(gmem), "r"(src_bytes));
}
__device__ __forceinline__ void cp_commit() {
    asm volatile("cp.async.commit_group;");
}
template <int N>
__device__ __forceinline__ void cp_wait() {
    asm volatile("cp.async.wait_group %0;" :: "n"(N));
}

__device__ __forceinline__ float4 ld4h(const __half* p) {
    uint2 r = *(const uint2*)p;
    float2 a = __half22float2(*(__half2*)&r.x);
    float2 b = __half22float2(*(__half2*)&r.y);
    return make_float4(a.x, a.y, b.x, b.y);
}

template <typename T>
__global__ __launch_bounds__(256) void k_gemm_tc(
    const T* __restrict__ A, const float* __restrict__ B,
    __half* __restrict__ C, int M, int K)
{
    constexpr bool ASYNC = (sizeof(T) == 4);
    __shared__ float As[2][GBM][GBK + 4];
    __shared__ float Bs[2][GBK][GBN];
    __shared__ __half Cs[GBM][CS_STRIDE];

    int tid = threadIdx.x;
    int warp = tid >> 5, lane = tid & 31;
    int wm = warp & 1;
    int wn = warp >> 1;
    int blockRow = blockIdx.x * GBM;

    int qr = lane >> 2;   // 0..7
    int qk = lane & 3;    // 0..3

    float4 c[4][2];
    #pragma unroll
    for (int i = 0; i < 4; i++)
        #pragma unroll
        for (int j = 0; j < 2; j++) c[i][j] = make_float4(0.f, 0.f, 0.f, 0.f);

    int ar = tid >> 2;            // 0..63 (rows ar, ar+64)
    int ac = (tid & 3) * 4;       // 0,4,8,12
    int br = tid >> 4;            // 0..15
    int bc = (tid & 15) * 4;      // 0..60

    auto load_async = [&](int k0, int st) {
        #pragma unroll
        for (int p = 0; p < 2; p++) {
            int r = ar + p * 64;
            int gr = blockRow + r;
            cp_async16(&As[st][r][ac], (const float*)A + (size_t)gr * K + k0 + ac,
                       (gr < M) ? 16 : 0);
        }
        cp_async16(&Bs[st][br][bc], B + (size_t)(k0 + br) * GBN + bc, 16);
    };

    auto load_sync = [&](int k0, int st) {
        #pragma unroll
        for (int p = 0; p < 2; p++) {
            int r = ar + p * 64;
            int gr = blockRow + r;
            float4 v = make_float4(0.f, 0.f, 0.f, 0.f);
            if (gr < M) v = ld4h((const __half*)A + (size_t)gr * K + k0 + ac);
            *(float4*)&As[st][r][ac] = v;
        }
        *(float4*)&Bs[st][br][bc] = *(const float4*)(B + (size_t)(k0 + br) * GBN + bc);
    };

    auto compute = [&](int st) {
        #pragma unroll
        for (int kk = 0; kk < 2; kk++) {
            int kb = kk * 8;
            uint32_t bf[2][2];
            #pragma unroll
            for (int ni = 0; ni < 2; ni++) {
                int n = wn * 16 + ni * 8 + qr;
                bf[ni][0] = f2tf32(Bs[st][kb + qk][n]);
                bf[ni][1] = f2tf32(Bs[st][kb + qk + 4][n]);
            }
            #pragma unroll
            for (int mi = 0; mi < 4; mi++) {
                int r0 = wm * 64 + mi * 16 + qr;
                uint32_t a0 = f2tf32(As[st][r0][kb + qk]);
                uint32_t a1 = f2tf32(As[st][r0 + 8][kb + qk]);
                uint32_t a2 = f2tf32(As[st][r0][kb + qk + 4]);
                uint32_t a3 = f2tf32(As[st][r0 + 8][kb + qk + 4]);
                mma_tf32(c[mi][0], a0, a1, a2, a3, bf[0][0], bf[0][1]);
                mma_tf32(c[mi][1], a0, a1, a2, a3, bf[1][0], bf[1][1]);
            }
        }
    };

    if constexpr (ASYNC) {
        load_async(0, 0);
        cp_commit();
        int buf = 0;
        for (int k0 = 0; k0 < K; k0 += GBK) {
            bool has_next = (k0 + GBK) < K;
            if (has_next) { load_async(k0 + GBK, buf ^ 1); cp_commit(); }
            if (has_next) cp_wait<1>(); else cp_wait<0>();
            __syncthreads();
            compute(buf);
            __syncthreads();
            buf ^= 1;
        }
    } else {
        for (int k0 = 0; k0 < K; k0 += GBK) {
            load_sync(k0, 0);
            __syncthreads();
            compute(0);
            __syncthreads();
        }
    }

    // epilogue: scale rows by dis[r], stage to smem, coalesced store
    #pragma unroll
    for (int mi = 0; mi < 4; mi++) {
        int rr0 = wm * 64 + mi * 16 + qr;
        int rr1 = rr0 + 8;
        int gr0 = blockRow + rr0, gr1 = blockRow + rr1;
        float d0 = (gr0 < M) ? g_dis[gr0] : 0.f;
        float d1 = (gr1 < M) ? g_dis[gr1] : 0.f;
        int ncol = wn * 16 + 2 * qk;
        #pragma unroll
        for (int ni = 0; ni < 2; ni++) {
            int n = ncol + ni * 8;
            *(__half2*)&Cs[rr0][n] = __floats2half2_rn(d0 * c[mi][ni].x, d0 * c[mi][ni].y);
            *(__half2*)&Cs[rr1][n] = __floats2half2_rn(d1 * c[mi][ni].z, d1 * c[mi][ni].w);
        }
    }
    __syncthreads();
    int cr = tid >> 3;
    int ccol = (tid & 7) * 8;
    #pragma unroll
    for (int p = 0; p < 4; p++) {
        int r = p * 32 + cr;
        int gr = blockRow + r;
        if (gr < M)
            *(uint4*)(C + (size_t)gr * HID + ccol) = *(uint4*)&Cs[r][ccol];
    }
}

// ---------------------------------------------------------------------------
// CSR pull over pre-scaled rows: out[i] = dis_i*(sum_s sh[s] + sh[i]) + bias
// quarter-warp per row (8 lanes x uint4 = 128 B); 4 rows in flight/quarter.
// ---------------------------------------------------------------------------
__device__ __forceinline__ void acc8(float* a, uint4 r) {
    __half2* h2 = (__half2*)&r;
    #pragma unroll
    for (int i = 0; i < 4; i++) {
        float2 f = __half22float2(h2[i]);
        a[2 * i] += f.x;
        a[2 * i + 1] += f.y;
    }
}

template <typename TO>
__global__ __launch_bounds__(256) void k_pull(
    const __half* __restrict__ h, const float* __restrict__ bias,
    TO* __restrict__ out, int M, int do_relu)
{
    int gw = (blockIdx.x * blockDim.x + threadIdx.x) >> 5;
    if (gw >= M) return;
    int lane = threadIdx.x & 31;
    int quarter = lane >> 3;   // 0..3
    int q = lane & 7;          // 0..7

    int start = g_row[gw];
    int end   = g_row[gw + 1];
    float dd = g_dis[gw];

    float acc[8];
    #pragma unroll
    for (int i = 0; i < 8; i++) acc[i] = 0.f;

    int j = start + quarter;
    for (; j + 12 < end; j += 16) {
        int s0 = __ldg(g_csr + j);
        int s1 = __ldg(g_csr + j + 4);
        int s2 = __ldg(g_csr + j + 8);
        int s3 = __ldg(g_csr + j + 12);
        uint4 r0 = *(const uint4*)(h + (size_t)s0 * HID + q * 8);
        uint4 r1 = *(const uint4*)(h + (size_t)s1 * HID + q * 8);
        uint4 r2 = *(const uint4*)(h + (size_t)s2 * HID + q * 8);
        uint4 r3 = *(const uint4*)(h + (size_t)s3 * HID + q * 8);
        acc8(acc, r0);
        acc8(acc, r1);
        acc8(acc, r2);
        acc8(acc, r3);
    }
    for (; j < end; j += 4) {
        int s = __ldg(g_csr + j);
        uint4 r = *(const uint4*)(h + (size_t)s * HID + q * 8);
        acc8(acc, r);
    }

    // combine quarters
    #pragma unroll
    for (int i = 0; i < 8; i++) {
        acc[i] += __shfl_xor_sync(0xffffffffu, acc[i], 8);
        acc[i] += __shfl_xor_sync(0xffffffffu, acc[i], 16);
    }

    if (quarter == 0) {
        uint4 rs = *(const uint4*)(h + (size_t)gw * HID + q * 8);
        acc8(acc, rs);   // self loop (already dis_i-scaled)
        float r[8];
        #pragma unroll
        for (int i = 0; i < 8; i++) {
            float bq = bias[q * 8 + i];
            r[i] = dd * acc[i] + bq;
            if (do_relu) r[i] = fmaxf(r[i], 0.f);
        }
        if constexpr (sizeof(TO) == 4) {
            float4 v0 = make_float4(r[0], r[1], r[2], r[3]);
            float4 v1 = make_float4(r[4], r[5], r[6], r[7]);
            *(float4*)((float*)out + (size_t)gw * HID + q * 8) = v0;
            *(float4*)((float*)out + (size_t)gw * HID + q * 8 + 4) = v1;
        } else {
            __half2 h2[4];
            #pragma unroll
            for (int i = 0; i < 4; i++)
                h2[i] = __floats2half2_rn(r[2 * i], r[2 * i + 1]);
            *(uint4*)((__half*)out + (size_t)gw * HID + q * 8) = *(uint4*)h2;
        }
    }
}

// ---------------------------------------------------------------------------
extern "C" void kernel_launch(void* const* d_in, const int* in_sizes, int n_in,
                              void* d_out, int out_size)
{
    const float* x  = (const float*)d_in[0];
    const int*   ei = (const int*)d_in[1];
    const float* W1 = (const float*)d_in[2];
    const float* b1 = (const float*)d_in[3];
    const float* W2 = (const float*)d_in[4];
    const float* b2 = (const float*)d_in[5];
    float* out = (float*)d_out;

    int M = in_sizes[0] / IN_DIM;
    int E = in_sizes[1] / 2;
    const int* src = ei;
    const int* dst = ei + E;

    __half *ph, *pagg;
    cudaGetSymbolAddress((void**)&ph, g_h);
    cudaGetSymbolAddress((void**)&pagg, g_agg);

    int tb = 256;
    int gM = (M + tb - 1) / tb;
    int gE4 = ((E + 3) / 4 + tb - 1) / tb;
    int gGemm = (M + GBM - 1) / GBM;
    int nParts = (M + SCAN_B - 1) / SCAN_B;
    long long pw = (long long)M * 32;
    int gPull = (int)((pw + tb - 1) / tb);

    // CSR build interleaved with layer-1 GEMM (gemm at slot 4 for profiling)
    k_zero_deg<<<gM, tb>>>(M);
    k_hist<<<gE4, tb>>>(dst, E);
    k_scan1<<<nParts, 256>>>(M);
    k_gemm_tc<float><<<gGemm, 256>>>(x, W1, ph, M, IN_DIM);
    k_scan3<<<nParts, 256>>>(M, E);
    k_fill<<<gE4, tb>>>(src, dst, E);

    k_pull<__half><<<gPull, tb>>>(ph, b1, pagg, M, 1);
    k_gemm_tc<__half><<<gGemm, 256>>>(pagg, W2, ph, M, HID);
    k_pull<float><<<gPull, tb>>>(ph, b2, out, M, 0);
}

// round 10
// speedup vs baseline: 3.3967x; 1.0739x over previous
#include <cuda_runtime.h>
#include <cuda_fp16.h>
#include <cstdint>

#define MAX_NODES 100000
#define MAX_EDGES 3200000
#define HID 64
#define IN_DIM 256
#define SCAN_B 1024
#define MAX_PARTS 128

// Scratch (allocation-free rule: device globals)
__device__ __half g_h[(size_t)MAX_NODES * HID];    // dis-scaled gemm outputs (gather buffer)
__device__ __half g_agg[(size_t)MAX_NODES * HID];  // fp16 pull1 output (gemm2 input)
__device__ float  g_dis[MAX_NODES];
__device__ int    g_deg[MAX_NODES];
__device__ int    g_row[MAX_NODES + 1];
__device__ int    g_cursor[MAX_NODES];
__device__ int    g_csr[MAX_EDGES];
__device__ int    g_part[MAX_PARTS];

// ---------------------------------------------------------------------------
// degree histogram (4 edges/thread, int4)
// ---------------------------------------------------------------------------
__global__ void k_zero_deg(int M) {
    int i = blockIdx.x * blockDim.x + threadIdx.x;
    if (i < M) g_deg[i] = 0;
}

__global__ void k_hist(const int* __restrict__ dst, int E) {
    int i = blockIdx.x * blockDim.x + threadIdx.x;
    int e = i * 4;
    if (e + 3 < E && (((uintptr_t)dst & 15) == 0)) {
        int4 d = *(const int4*)(dst + e);
        atomicAdd(&g_deg[d.x], 1);
        atomicAdd(&g_deg[d.y], 1);
        atomicAdd(&g_deg[d.z], 1);
        atomicAdd(&g_deg[d.w], 1);
    } else {
        for (int k = e; k < E && k < e + 4; k++)
            atomicAdd(&g_deg[dst[k]], 1);
    }
}

// ---------------------------------------------------------------------------
// scan1: block-local exclusive scan + dis
// ---------------------------------------------------------------------------
__global__ __launch_bounds__(256) void k_scan1(int M) {
    __shared__ int wsum[8], wexcl[8];
    int b = blockIdx.x, t = threadIdx.x;
    int base = b * SCAN_B + t * 4;
    int v[4], s = 0;
    #pragma unroll
    for (int i = 0; i < 4; i++) {
        v[i] = (base + i < M) ? g_deg[base + i] : 0;
        s += v[i];
    }
    #pragma unroll
    for (int i = 0; i < 4; i++)
        if (base + i < M) g_dis[base + i] = rsqrtf((float)v[i] + 1.0f);
    int lane = t & 31, wid = t >> 5;
    int x = s;
    #pragma unroll
    for (int off = 1; off < 32; off <<= 1) {
        int y = __shfl_up_sync(0xffffffffu, x, off);
        if (lane >= off) x += y;
    }
    if (lane == 31) wsum[wid] = x;
    __syncthreads();
    if (t == 0) {
        int r = 0;
        #pragma unroll
        for (int w = 0; w < 8; w++) { wexcl[w] = r; r += wsum[w]; }
        g_part[b] = r;
    }
    __syncthreads();
    int run = wexcl[wid] + (x - s);
    #pragma unroll
    for (int i = 0; i < 4; i++) {
        if (base + i < M) g_row[base + i] = run;
        run += v[i];
    }
}

// scan3: each block computes its own partial prefix (<=98 ints) and applies it
__global__ __launch_bounds__(256) void k_scan3(int M, int E) {
    __shared__ int s_off;
    int b = blockIdx.x, t = threadIdx.x;
    if (t < 32) {
        int s = 0;
        for (int i = t; i < b; i += 32) s += g_part[i];
        #pragma unroll
        for (int o = 16; o; o >>= 1) s += __shfl_xor_sync(0xffffffffu, s, o);
        if (t == 0) s_off = s;
    }
    __syncthreads();
    int off = s_off;
    int base = b * SCAN_B + t * 4;
    #pragma unroll
    for (int i = 0; i < 4; i++) {
        int idx = base + i;
        if (idx < M) {
            int r = g_row[idx] + off;
            g_row[idx] = r;
            g_cursor[idx] = r;
        }
    }
    if (b == 0 && t == 0) g_row[M] = E;
}

__global__ void k_fill(const int* __restrict__ src, const int* __restrict__ dst, int E) {
    int i = blockIdx.x * blockDim.x + threadIdx.x;
    int e = i * 4;
    if (e + 3 < E && (((uintptr_t)src & 15) == 0) && (((uintptr_t)dst & 15) == 0)) {
        int4 s = *(const int4*)(src + e);
        int4 d = *(const int4*)(dst + e);
        g_csr[atomicAdd(&g_cursor[d.x], 1)] = s.x;
        g_csr[atomicAdd(&g_cursor[d.y], 1)] = s.y;
        g_csr[atomicAdd(&g_cursor[d.z], 1)] = s.z;
        g_csr[atomicAdd(&g_cursor[d.w], 1)] = s.w;
    } else {
        for (int k = e; k < E && k < e + 4; k++)
            g_csr[atomicAdd(&g_cursor[dst[k]], 1)] = src[k];
    }
}

// ---------------------------------------------------------------------------
// fp16 HMMA GEMM: C[M x 64](fp16, row-scaled by dis) = A[M x K] * B[K x 64]
// BM=128 BN=64 BK=16; 8 warps; warp tile 64x16; mma.m16n8k16 + ldmatrix.
// fp16 smem tiles, register-prefetch global loads (fp32->fp16 on load).
// ---------------------------------------------------------------------------
#define GBM 128
#define GBN 64
#define GBK 16
#define AST 24               // Ah row stride (halfs): 48 B -> 12-bank stride
#define BST 72               // Bh row stride (halfs): 144 B -> 4-bank stride
#define CS_STRIDE (HID + 8)

__device__ __forceinline__ uint32_t smem_u32(const void* p) {
    return (uint32_t)__cvta_generic_to_shared(p);
}

__device__ __forceinline__ void ldsm_x4(uint32_t& r0, uint32_t& r1, uint32_t& r2, uint32_t& r3, uint32_t a) {
    asm volatile("ldmatrix.sync.aligned.m8n8.x4.shared.b16 {%0,%1,%2,%3}, [%4];"
                 : "=r"(r0), "=r"(r1), "=r"(r2), "=r"(r3) : "r"(a));
}
__device__ __forceinline__ void ldsm_x4t(uint32_t& r0, uint32_t& r1, uint32_t& r2, uint32_t& r3, uint32_t a) {
    asm volatile("ldmatrix.sync.aligned.m8n8.x4.trans.shared.b16 {%0,%1,%2,%3}, [%4];"
                 : "=r"(r0), "=r"(r1), "=r"(r2), "=r"(r3) : "r"(a));
}

__device__ __forceinline__ void mma_f16(float4& c,
    uint32_t a0, uint32_t a1, uint32_t a2, uint32_t a3,
    uint32_t b0, uint32_t b1)
{
    asm volatile(
        "mma.sync.aligned.m16n8k16.row.col.f32.f16.f16.f32 "
        "{%0,%1,%2,%3}, {%4,%5,%6,%7}, {%8,%9}, {%0,%1,%2,%3};"
        : "+f"(c.x), "+f"(c.y), "+f"(c.z), "+f"(c.w)
        : "r"(a0), "r"(a1), "r"(a2), "r"(a3), "r"(b0), "r"(b1));
}

template <typename T>
__global__ __launch_bounds__(256) void k_gemm_tc(
    const T* __restrict__ A, const float* __restrict__ B,
    __half* __restrict__ C, int M, int K)
{
    constexpr bool F32IN = (sizeof(T) == 4);
    __shared__ __half Ah[GBM][AST];
    __shared__ __half Bh[GBK][BST];
    __shared__ __half Cs[GBM][CS_STRIDE];

    int tid = threadIdx.x;
    int warp = tid >> 5, lane = tid & 31;
    int wm = warp & 1;    // 2 x 64 rows
    int wn = warp >> 1;   // 4 x 16 cols
    int blockRow = blockIdx.x * GBM;

    int qr = lane >> 2;   // 0..7
    int qk = lane & 3;    // 0..3

    float4 c[4][2];
    #pragma unroll
    for (int i = 0; i < 4; i++)
        #pragma unroll
        for (int j = 0; j < 2; j++) c[i][j] = make_float4(0.f, 0.f, 0.f, 0.f);

    // ldmatrix fragment smem addresses (fixed: single smem buffer, reg prefetch)
    uint32_t a_addr[4];
    #pragma unroll
    for (int mi = 0; mi < 4; mi++) {
        int row = wm * 64 + mi * 16 + (lane & 7) + ((lane >> 3) & 1) * 8;
        int col = (lane >> 4) * 8;
        a_addr[mi] = smem_u32(&Ah[row][col]);
    }
    uint32_t b_addr = smem_u32(&Bh[lane & 15][wn * 16 + (lane >> 4) * 8]);

    // global->smem maps
    int ar = tid >> 2;            // fp32 A: rows ar, ar+64
    int ac = (tid & 3) * 4;       // 0,4,8,12
    int rh = tid >> 1;            // fp16 A: row
    int ch = (tid & 1) * 8;       // 0,8
    int br = tid >> 4;            // 0..15
    int bc = (tid & 15) * 4;      // 0..60

    float4 ra0, ra1, rb;
    uint4 rha;

    auto load_g = [&](int k0) {
        if constexpr (F32IN) {
            int gr0 = blockRow + ar, gr1 = gr0 + 64;
            ra0 = (gr0 < M) ? *(const float4*)((const float*)A + (size_t)gr0 * K + k0 + ac)
                            : make_float4(0.f, 0.f, 0.f, 0.f);
            ra1 = (gr1 < M) ? *(const float4*)((const float*)A + (size_t)gr1 * K + k0 + ac)
                            : make_float4(0.f, 0.f, 0.f, 0.f);
        } else {
            int gr = blockRow + rh;
            rha = (gr < M) ? *(const uint4*)((const __half*)A + (size_t)gr * K + k0 + ch)
                           : make_uint4(0u, 0u, 0u, 0u);
        }
        rb = *(const float4*)(B + (size_t)(k0 + br) * GBN + bc);
    };

    auto store_s = [&]() {
        if constexpr (F32IN) {
            __half2 h0 = __floats2half2_rn(ra0.x, ra0.y);
            __half2 h1 = __floats2half2_rn(ra0.z, ra0.w);
            uint2 u; u.x = *(uint32_t*)&h0; u.y = *(uint32_t*)&h1;
            *(uint2*)&Ah[ar][ac] = u;
            h0 = __floats2half2_rn(ra1.x, ra1.y);
            h1 = __floats2half2_rn(ra1.z, ra1.w);
            u.x = *(uint32_t*)&h0; u.y = *(uint32_t*)&h1;
            *(uint2*)&Ah[ar + 64][ac] = u;
        } else {
            *(uint4*)&Ah[rh][ch] = rha;
        }
        __half2 b0 = __floats2half2_rn(rb.x, rb.y);
        __half2 b1 = __floats2half2_rn(rb.z, rb.w);
        uint2 ub; ub.x = *(uint32_t*)&b0; ub.y = *(uint32_t*)&b1;
        *(uint2*)&Bh[br][bc] = ub;
    };

    auto compute = [&]() {
        uint32_t bb0, bb1, bb2, bb3;
        ldsm_x4t(bb0, bb1, bb2, bb3, b_addr);
        #pragma unroll
        for (int mi = 0; mi < 4; mi++) {
            uint32_t a0, a1, a2, a3;
            ldsm_x4(a0, a1, a2, a3, a_addr[mi]);
            mma_f16(c[mi][0], a0, a1, a2, a3, bb0, bb1);
            mma_f16(c[mi][1], a0, a1, a2, a3, bb2, bb3);
        }
    };

    load_g(0);
    for (int k0 = 0; k0 < K; k0 += GBK) {
        store_s();
        __syncthreads();
        if (k0 + GBK < K) load_g(k0 + GBK);
        compute();
        __syncthreads();
    }

    // epilogue: scale rows by dis[r], stage to smem, coalesced store
    #pragma unroll
    for (int mi = 0; mi < 4; mi++) {
        int rr0 = wm * 64 + mi * 16 + qr;
        int rr1 = rr0 + 8;
        int gr0 = blockRow + rr0, gr1 = blockRow + rr1;
        float d0 = (gr0 < M) ? g_dis[gr0] : 0.f;
        float d1 = (gr1 < M) ? g_dis[gr1] : 0.f;
        int ncol = wn * 16 + 2 * qk;
        #pragma unroll
        for (int ni = 0; ni < 2; ni++) {
            int n = ncol + ni * 8;
            *(__half2*)&Cs[rr0][n] = __floats2half2_rn(d0 * c[mi][ni].x, d0 * c[mi][ni].y);
            *(__half2*)&Cs[rr1][n] = __floats2half2_rn(d1 * c[mi][ni].z, d1 * c[mi][ni].w);
        }
    }
    __syncthreads();
    int cr = tid >> 3;
    int ccol = (tid & 7) * 8;
    #pragma unroll
    for (int p = 0; p < 4; p++) {
        int r = p * 32 + cr;
        int gr = blockRow + r;
        if (gr < M)
            *(uint4*)(C + (size_t)gr * HID + ccol) = *(uint4*)&Cs[r][ccol];
    }
}

// ---------------------------------------------------------------------------
// CSR pull over pre-scaled rows: out[i] = dis_i*(sum_s sh[s] + sh[i]) + bias
// quarter-warp per row (8 lanes x uint4 = 128 B); 4 rows in flight/quarter.
// ---------------------------------------------------------------------------
__device__ __forceinline__ void acc8(float* a, uint4 r) {
    __half2* h2 = (__half2*)&r;
    #pragma unroll
    for (int i = 0; i < 4; i++) {
        float2 f = __half22float2(h2[i]);
        a[2 * i] += f.x;
        a[2 * i + 1] += f.y;
    }
}

template <typename TO>
__global__ __launch_bounds__(256) void k_pull(
    const __half* __restrict__ h, const float* __restrict__ bias,
    TO* __restrict__ out, int M, int do_relu)
{
    int gw = (blockIdx.x * blockDim.x + threadIdx.x) >> 5;
    if (gw >= M) return;
    int lane = threadIdx.x & 31;
    int quarter = lane >> 3;   // 0..3
    int q = lane & 7;          // 0..7

    int start = g_row[gw];
    int end   = g_row[gw + 1];
    float dd = g_dis[gw];

    float acc[8];
    #pragma unroll
    for (int i = 0; i < 8; i++) acc[i] = 0.f;

    int j = start + quarter;
    for (; j + 12 < end; j += 16) {
        int s0 = __ldg(g_csr + j);
        int s1 = __ldg(g_csr + j + 4);
        int s2 = __ldg(g_csr + j + 8);
        int s3 = __ldg(g_csr + j + 12);
        uint4 r0 = *(const uint4*)(h + (size_t)s0 * HID + q * 8);
        uint4 r1 = *(const uint4*)(h + (size_t)s1 * HID + q * 8);
        uint4 r2 = *(const uint4*)(h + (size_t)s2 * HID + q * 8);
        uint4 r3 = *(const uint4*)(h + (size_t)s3 * HID + q * 8);
        acc8(acc, r0);
        acc8(acc, r1);
        acc8(acc, r2);
        acc8(acc, r3);
    }
    for (; j < end; j += 4) {
        int s = __ldg(g_csr + j);
        uint4 r = *(const uint4*)(h + (size_t)s * HID + q * 8);
        acc8(acc, r);
    }

    // combine quarters
    #pragma unroll
    for (int i = 0; i < 8; i++) {
        acc[i] += __shfl_xor_sync(0xffffffffu, acc[i], 8);
        acc[i] += __shfl_xor_sync(0xffffffffu, acc[i], 16);
    }

    if (quarter == 0) {
        uint4 rs = *(const uint4*)(h + (size_t)gw * HID + q * 8);
        acc8(acc, rs);   // self loop (already dis_i-scaled)
        float r[8];
        #pragma unroll
        for (int i = 0; i < 8; i++) {
            float bq = bias[q * 8 + i];
            r[i] = dd * acc[i] + bq;
            if (do_relu) r[i] = fmaxf(r[i], 0.f);
        }
        if constexpr (sizeof(TO) == 4) {
            float4 v0 = make_float4(r[0], r[1], r[2], r[3]);
            float4 v1 = make_float4(r[4], r[5], r[6], r[7]);
            *(float4*)((float*)out + (size_t)gw * HID + q * 8) = v0;
            *(float4*)((float*)out + (size_t)gw * HID + q * 8 + 4) = v1;
        } else {
            __half2 h2[4];
            #pragma unroll
            for (int i = 0; i < 4; i++)
                h2[i] = __floats2half2_rn(r[2 * i], r[2 * i + 1]);
            *(uint4*)((__half*)out + (size_t)gw * HID + q * 8) = *(uint4*)h2;
        }
    }
}

// ---------------------------------------------------------------------------
extern "C" void kernel_launch(void* const* d_in, const int* in_sizes, int n_in,
                              void* d_out, int out_size)
{
    const float* x  = (const float*)d_in[0];
    const int*   ei = (const int*)d_in[1];
    const float* W1 = (const float*)d_in[2];
    const float* b1 = (const float*)d_in[3];
    const float* W2 = (const float*)d_in[4];
    const float* b2 = (const float*)d_in[5];
    float* out = (float*)d_out;

    int M = in_sizes[0] / IN_DIM;
    int E = in_sizes[1] / 2;
    const int* src = ei;
    const int* dst = ei + E;

    __half *ph, *pagg;
    cudaGetSymbolAddress((void**)&ph, g_h);
    cudaGetSymbolAddress((void**)&pagg, g_agg);

    int tb = 256;
    int gM = (M + tb - 1) / tb;
    int gE4 = ((E + 3) / 4 + tb - 1) / tb;
    int gGemm = (M + GBM - 1) / GBM;
    int nParts = (M + SCAN_B - 1) / SCAN_B;
    long long pw = (long long)M * 32;
    int gPull = (int)((pw + tb - 1) / tb);

    // CSR build interleaved with layer-1 GEMM (gemm at slot 4 for profiling)
    k_zero_deg<<<gM, tb>>>(M);
    k_hist<<<gE4, tb>>>(dst, E);
    k_scan1<<<nParts, 256>>>(M);
    k_gemm_tc<float><<<gGemm, 256>>>(x, W1, ph, M, IN_DIM);
    k_scan3<<<nParts, 256>>>(M, E);
    k_fill<<<gE4, tb>>>(src, dst, E);

    k_pull<__half><<<gPull, tb>>>(ph, b1, pagg, M, 1);
    k_gemm_tc<__half><<<gGemm, 256>>>(pagg, W2, ph, M, HID);
    k_pull<float><<<gPull, tb>>>(ph, b2, out, M, 0);
}

// round 11
// speedup vs baseline: 3.5344x; 1.0406x over previous
#include <cuda_runtime.h>
#include <cuda_fp16.h>
#include <cstdint>

#define MAX_NODES 100000
#define MAX_EDGES 3200000
#define HID 64
#define IN_DIM 256
#define SCAN_B 1024
#define MAX_PARTS 128

// Scratch (allocation-free rule: device globals)
__device__ __half g_h[(size_t)MAX_NODES * HID];    // dis-scaled gemm outputs (gather buffer)
__device__ __half g_agg[(size_t)MAX_NODES * HID];  // fp16 pull1 output (gemm2 input)
__device__ __half g_w1h[IN_DIM * HID];             // fp16 W1
__device__ __half g_w2h[HID * HID];                // fp16 W2
__device__ float  g_dis[MAX_NODES];
__device__ int    g_deg[MAX_NODES];
__device__ int    g_row[MAX_NODES + 1];
__device__ int    g_cursor[MAX_NODES];
__device__ int    g_csr[MAX_EDGES];
__device__ int    g_part[MAX_PARTS];

// ---------------------------------------------------------------------------
// zero degree + convert weights to fp16 (fused; launch #1)
// ---------------------------------------------------------------------------
__global__ void k_zero_deg(int M, const float* __restrict__ W1, const float* __restrict__ W2) {
    int i = blockIdx.x * blockDim.x + threadIdx.x;
    if (i < M) g_deg[i] = 0;
    if (i < IN_DIM * HID) g_w1h[i] = __float2half(W1[i]);
    if (i < HID * HID)    g_w2h[i] = __float2half(W2[i]);
}

__global__ void k_hist(const int* __restrict__ dst, int E) {
    int i = blockIdx.x * blockDim.x + threadIdx.x;
    int e = i * 4;
    if (e + 3 < E && (((uintptr_t)dst & 15) == 0)) {
        int4 d = *(const int4*)(dst + e);
        atomicAdd(&g_deg[d.x], 1);
        atomicAdd(&g_deg[d.y], 1);
        atomicAdd(&g_deg[d.z], 1);
        atomicAdd(&g_deg[d.w], 1);
    } else {
        for (int k = e; k < E && k < e + 4; k++)
            atomicAdd(&g_deg[dst[k]], 1);
    }
}

// ---------------------------------------------------------------------------
// scan1: block-local exclusive scan + dis
// ---------------------------------------------------------------------------
__global__ __launch_bounds__(256) void k_scan1(int M) {
    __shared__ int wsum[8], wexcl[8];
    int b = blockIdx.x, t = threadIdx.x;
    int base = b * SCAN_B + t * 4;
    int v[4], s = 0;
    #pragma unroll
    for (int i = 0; i < 4; i++) {
        v[i] = (base + i < M) ? g_deg[base + i] : 0;
        s += v[i];
    }
    #pragma unroll
    for (int i = 0; i < 4; i++)
        if (base + i < M) g_dis[base + i] = rsqrtf((float)v[i] + 1.0f);
    int lane = t & 31, wid = t >> 5;
    int x = s;
    #pragma unroll
    for (int off = 1; off < 32; off <<= 1) {
        int y = __shfl_up_sync(0xffffffffu, x, off);
        if (lane >= off) x += y;
    }
    if (lane == 31) wsum[wid] = x;
    __syncthreads();
    if (t == 0) {
        int r = 0;
        #pragma unroll
        for (int w = 0; w < 8; w++) { wexcl[w] = r; r += wsum[w]; }
        g_part[b] = r;
    }
    __syncthreads();
    int run = wexcl[wid] + (x - s);
    #pragma unroll
    for (int i = 0; i < 4; i++) {
        if (base + i < M) g_row[base + i] = run;
        run += v[i];
    }
}

// scan3: each block computes its own partial prefix (<=98 ints) and applies it
__global__ __launch_bounds__(256) void k_scan3(int M, int E) {
    __shared__ int s_off;
    int b = blockIdx.x, t = threadIdx.x;
    if (t < 32) {
        int s = 0;
        for (int i = t; i < b; i += 32) s += g_part[i];
        #pragma unroll
        for (int o = 16; o; o >>= 1) s += __shfl_xor_sync(0xffffffffu, s, o);
        if (t == 0) s_off = s;
    }
    __syncthreads();
    int off = s_off;
    int base = b * SCAN_B + t * 4;
    #pragma unroll
    for (int i = 0; i < 4; i++) {
        int idx = base + i;
        if (idx < M) {
            int r = g_row[idx] + off;
            g_row[idx] = r;
            g_cursor[idx] = r;
        }
    }
    if (b == 0 && t == 0) g_row[M] = E;
}

__global__ void k_fill(const int* __restrict__ src, const int* __restrict__ dst, int E) {
    int i = blockIdx.x * blockDim.x + threadIdx.x;
    int e = i * 4;
    if (e + 3 < E && (((uintptr_t)src & 15) == 0) && (((uintptr_t)dst & 15) == 0)) {
        int4 s = *(const int4*)(src + e);
        int4 d = *(const int4*)(dst + e);
        g_csr[atomicAdd(&g_cursor[d.x], 1)] = s.x;
        g_csr[atomicAdd(&g_cursor[d.y], 1)] = s.y;
        g_csr[atomicAdd(&g_cursor[d.z], 1)] = s.z;
        g_csr[atomicAdd(&g_cursor[d.w], 1)] = s.w;
    } else {
        for (int k = e; k < E && k < e + 4; k++)
            g_csr[atomicAdd(&g_cursor[dst[k]], 1)] = src[k];
    }
}

// ---------------------------------------------------------------------------
// fp16 HMMA GEMM: C[M x 64](fp16, row-scaled by dis) = A[M x K] * B[K x 64]
// BM=128 BN=64 BK=32; 8 warps; mma.m16n8k16 + ldmatrix; fp16 weights.
// Register-prefetch global loads; 8 (K=256) / 2 (K=64) iterations.
// ---------------------------------------------------------------------------
#define GBM 128
#define GBN 64
#define GBK 32
#define AST 40               // Ah row stride (halfs): 80 B -> 20-bank stride
#define BST 72               // Bh row stride (halfs): 144 B -> 4-bank stride
#define CS_STRIDE (HID + 8)

__device__ __forceinline__ uint32_t smem_u32(const void* p) {
    return (uint32_t)__cvta_generic_to_shared(p);
}

__device__ __forceinline__ void ldsm_x4(uint32_t& r0, uint32_t& r1, uint32_t& r2, uint32_t& r3, uint32_t a) {
    asm volatile("ldmatrix.sync.aligned.m8n8.x4.shared.b16 {%0,%1,%2,%3}, [%4];"
                 : "=r"(r0), "=r"(r1), "=r"(r2), "=r"(r3) : "r"(a));
}
__device__ __forceinline__ void ldsm_x4t(uint32_t& r0, uint32_t& r1, uint32_t& r2, uint32_t& r3, uint32_t a) {
    asm volatile("ldmatrix.sync.aligned.m8n8.x4.trans.shared.b16 {%0,%1,%2,%3}, [%4];"
                 : "=r"(r0), "=r"(r1), "=r"(r2), "=r"(r3) : "r"(a));
}

__device__ __forceinline__ void mma_f16(float4& c,
    uint32_t a0, uint32_t a1, uint32_t a2, uint32_t a3,
    uint32_t b0, uint32_t b1)
{
    asm volatile(
        "mma.sync.aligned.m16n8k16.row.col.f32.f16.f16.f32 "
        "{%0,%1,%2,%3}, {%4,%5,%6,%7}, {%8,%9}, {%0,%1,%2,%3};"
        : "+f"(c.x), "+f"(c.y), "+f"(c.z), "+f"(c.w)
        : "r"(a0), "r"(a1), "r"(a2), "r"(a3), "r"(b0), "r"(b1));
}

template <typename T>
__global__ __launch_bounds__(256) void k_gemm_tc(
    const T* __restrict__ A, const __half* __restrict__ B,
    __half* __restrict__ C, int M, int K)
{
    constexpr bool F32IN = (sizeof(T) == 4);
    __shared__ __half Ah[GBM][AST];
    __shared__ __half Bh[GBK][BST];
    __shared__ __half Cs[GBM][CS_STRIDE];

    int tid = threadIdx.x;
    int warp = tid >> 5, lane = tid & 31;
    int wm = warp & 1;    // 2 x 64 rows
    int wn = warp >> 1;   // 4 x 16 cols
    int blockRow = blockIdx.x * GBM;

    int qr = lane >> 2;   // 0..7
    int qk = lane & 3;    // 0..3

    float4 c[4][2];
    #pragma unroll
    for (int i = 0; i < 4; i++)
        #pragma unroll
        for (int j = 0; j < 2; j++) c[i][j] = make_float4(0.f, 0.f, 0.f, 0.f);

    // ldmatrix fragment smem addresses
    uint32_t a_addr[4];
    #pragma unroll
    for (int mi = 0; mi < 4; mi++) {
        int row = wm * 64 + mi * 16 + (lane & 7) + ((lane >> 3) & 1) * 8;
        int col = (lane >> 4) * 8;
        a_addr[mi] = smem_u32(&Ah[row][col]);
    }
    uint32_t b_addr = smem_u32(&Bh[lane & 15][wn * 16 + (lane >> 4) * 8]);

    // global->smem maps
    int ar4 = tid >> 3;           // fp32 A: rows ar4 + 32p, p=0..3
    int ac = (tid & 7) * 4;       // 0..28
    int rh = tid >> 1;            // fp16 A: row 0..127
    int ch = (tid & 1) * 16;      // 0,16
    int brh = tid >> 3;           // B: row 0..31
    int bch = (tid & 7) * 8;      // 0..56

    float4 ra[4];
    uint4 rha0, rha1;
    uint4 rbv;

    auto load_g = [&](int k0) {
        if constexpr (F32IN) {
            #pragma unroll
            for (int p = 0; p < 4; p++) {
                int gr = blockRow + ar4 + 32 * p;
                ra[p] = (gr < M) ? *(const float4*)((const float*)A + (size_t)gr * K + k0 + ac)
                                 : make_float4(0.f, 0.f, 0.f, 0.f);
            }
        } else {
            int gr = blockRow + rh;
            if (gr < M) {
                rha0 = *(const uint4*)((const __half*)A + (size_t)gr * K + k0 + ch);
                rha1 = *(const uint4*)((const __half*)A + (size_t)gr * K + k0 + ch + 8);
            } else {
                rha0 = make_uint4(0u, 0u, 0u, 0u);
                rha1 = make_uint4(0u, 0u, 0u, 0u);
            }
        }
        rbv = *(const uint4*)(B + (size_t)(k0 + brh) * GBN + bch);
    };

    auto store_s = [&]() {
        if constexpr (F32IN) {
            #pragma unroll
            for (int p = 0; p < 4; p++) {
                __half2 h0 = __floats2half2_rn(ra[p].x, ra[p].y);
                __half2 h1 = __floats2half2_rn(ra[p].z, ra[p].w);
                uint2 u; u.x = *(uint32_t*)&h0; u.y = *(uint32_t*)&h1;
                *(uint2*)&Ah[ar4 + 32 * p][ac] = u;
            }
        } else {
            *(uint4*)&Ah[rh][ch] = rha0;
            *(uint4*)&Ah[rh][ch + 8] = rha1;
        }
        *(uint4*)&Bh[brh][bch] = rbv;
    };

    auto compute = [&]() {
        #pragma unroll
        for (int kk = 0; kk < 2; kk++) {
            uint32_t bb0, bb1, bb2, bb3;
            ldsm_x4t(bb0, bb1, bb2, bb3, b_addr + kk * 16 * BST * 2);
            #pragma unroll
            for (int mi = 0; mi < 4; mi++) {
                uint32_t a0, a1, a2, a3;
                ldsm_x4(a0, a1, a2, a3, a_addr[mi] + kk * 32);
                mma_f16(c[mi][0], a0, a1, a2, a3, bb0, bb1);
                mma_f16(c[mi][1], a0, a1, a2, a3, bb2, bb3);
            }
        }
    };

    load_g(0);
    for (int k0 = 0; k0 < K; k0 += GBK) {
        store_s();
        __syncthreads();
        if (k0 + GBK < K) load_g(k0 + GBK);
        compute();
        __syncthreads();
    }

    // epilogue: scale rows by dis[r], stage to smem, coalesced store
    #pragma unroll
    for (int mi = 0; mi < 4; mi++) {
        int rr0 = wm * 64 + mi * 16 + qr;
        int rr1 = rr0 + 8;
        int gr0 = blockRow + rr0, gr1 = blockRow + rr1;
        float d0 = (gr0 < M) ? g_dis[gr0] : 0.f;
        float d1 = (gr1 < M) ? g_dis[gr1] : 0.f;
        int ncol = wn * 16 + 2 * qk;
        #pragma unroll
        for (int ni = 0; ni < 2; ni++) {
            int n = ncol + ni * 8;
            *(__half2*)&Cs[rr0][n] = __floats2half2_rn(d0 * c[mi][ni].x, d0 * c[mi][ni].y);
            *(__half2*)&Cs[rr1][n] = __floats2half2_rn(d1 * c[mi][ni].z, d1 * c[mi][ni].w);
        }
    }
    __syncthreads();
    int cr = tid >> 3;
    int ccol = (tid & 7) * 8;
    #pragma unroll
    for (int p = 0; p < 4; p++) {
        int r = p * 32 + cr;
        int gr = blockRow + r;
        if (gr < M)
            *(uint4*)(C + (size_t)gr * HID + ccol) = *(uint4*)&Cs[r][ccol];
    }
}

// ---------------------------------------------------------------------------
// CSR pull over pre-scaled rows: out[i] = dis_i*(sum_s sh[s] + sh[i]) + bias
// quarter-warp per row (8 lanes x uint4 = 128 B); 4 rows in flight/quarter.
// ---------------------------------------------------------------------------
__device__ __forceinline__ void acc8(float* a, uint4 r) {
    __half2* h2 = (__half2*)&r;
    #pragma unroll
    for (int i = 0; i < 4; i++) {
        float2 f = __half22float2(h2[i]);
        a[2 * i] += f.x;
        a[2 * i + 1] += f.y;
    }
}

template <typename TO>
__global__ __launch_bounds__(256) void k_pull(
    const __half* __restrict__ h, const float* __restrict__ bias,
    TO* __restrict__ out, int M, int do_relu)
{
    int gw = (blockIdx.x * blockDim.x + threadIdx.x) >> 5;
    if (gw >= M) return;
    int lane = threadIdx.x & 31;
    int quarter = lane >> 3;   // 0..3
    int q = lane & 7;          // 0..7

    int start = g_row[gw];
    int end   = g_row[gw + 1];
    float dd = g_dis[gw];

    float acc[8];
    #pragma unroll
    for (int i = 0; i < 8; i++) acc[i] = 0.f;

    int j = start + quarter;
    for (; j + 12 < end; j += 16) {
        int s0 = __ldg(g_csr + j);
        int s1 = __ldg(g_csr + j + 4);
        int s2 = __ldg(g_csr + j + 8);
        int s3 = __ldg(g_csr + j + 12);
        uint4 r0 = *(const uint4*)(h + (size_t)s0 * HID + q * 8);
        uint4 r1 = *(const uint4*)(h + (size_t)s1 * HID + q * 8);
        uint4 r2 = *(const uint4*)(h + (size_t)s2 * HID + q * 8);
        uint4 r3 = *(const uint4*)(h + (size_t)s3 * HID + q * 8);
        acc8(acc, r0);
        acc8(acc, r1);
        acc8(acc, r2);
        acc8(acc, r3);
    }
    for (; j < end; j += 4) {
        int s = __ldg(g_csr + j);
        uint4 r = *(const uint4*)(h + (size_t)s * HID + q * 8);
        acc8(acc, r);
    }

    // combine quarters
    #pragma unroll
    for (int i = 0; i < 8; i++) {
        acc[i] += __shfl_xor_sync(0xffffffffu, acc[i], 8);
        acc[i] += __shfl_xor_sync(0xffffffffu, acc[i], 16);
    }

    if (quarter == 0) {
        uint4 rs = *(const uint4*)(h + (size_t)gw * HID + q * 8);
        acc8(acc, rs);   // self loop (already dis_i-scaled)
        float r[8];
        #pragma unroll
        for (int i = 0; i < 8; i++) {
            float bq = bias[q * 8 + i];
            r[i] = dd * acc[i] + bq;
            if (do_relu) r[i] = fmaxf(r[i], 0.f);
        }
        if constexpr (sizeof(TO) == 4) {
            float4 v0 = make_float4(r[0], r[1], r[2], r[3]);
            float4 v1 = make_float4(r[4], r[5], r[6], r[7]);
            *(float4*)((float*)out + (size_t)gw * HID + q * 8) = v0;
            *(float4*)((float*)out + (size_t)gw * HID + q * 8 + 4) = v1;
        } else {
            __half2 h2[4];
            #pragma unroll
            for (int i = 0; i < 4; i++)
                h2[i] = __floats2half2_rn(r[2 * i], r[2 * i + 1]);
            *(uint4*)((__half*)out + (size_t)gw * HID + q * 8) = *(uint4*)h2;
        }
    }
}

// ---------------------------------------------------------------------------
extern "C" void kernel_launch(void* const* d_in, const int* in_sizes, int n_in,
                              void* d_out, int out_size)
{
    const float* x  = (const float*)d_in[0];
    const int*   ei = (const int*)d_in[1];
    const float* W1 = (const float*)d_in[2];
    const float* b1 = (const float*)d_in[3];
    const float* W2 = (const float*)d_in[4];
    const float* b2 = (const float*)d_in[5];
    float* out = (float*)d_out;

    int M = in_sizes[0] / IN_DIM;
    int E = in_sizes[1] / 2;
    const int* src = ei;
    const int* dst = ei + E;

    __half *ph, *pagg, *pw1, *pw2;
    cudaGetSymbolAddress((void**)&ph, g_h);
    cudaGetSymbolAddress((void**)&pagg, g_agg);
    cudaGetSymbolAddress((void**)&pw1, g_w1h);
    cudaGetSymbolAddress((void**)&pw2, g_w2h);

    int tb = 256;
    int gM = (M + tb - 1) / tb;
    int gE4 = ((E + 3) / 4 + tb - 1) / tb;
    int gGemm = (M + GBM - 1) / GBM;
    int nParts = (M + SCAN_B - 1) / SCAN_B;
    long long pw_ = (long long)M * 32;
    int gPull = (int)((pw_ + tb - 1) / tb);

    // CSR build interleaved with layer-1 GEMM (gemm at slot 4 for profiling)
    k_zero_deg<<<gM, tb>>>(M, W1, W2);
    k_hist<<<gE4, tb>>>(dst, E);
    k_scan1<<<nParts, 256>>>(M);
    k_gemm_tc<float><<<gGemm, 256>>>(x, pw1, ph, M, IN_DIM);
    k_scan3<<<nParts, 256>>>(M, E);
    k_fill<<<gE4, tb>>>(src, dst, E);

    k_pull<__half><<<gPull, tb>>>(ph, b1, pagg, M, 1);
    k_gemm_tc<__half><<<gGemm, 256>>>(pagg, pw2, ph, M, HID);
    k_pull<float><<<gPull, tb>>>(ph, b2, out, M, 0);
}